// round 13
// baseline (speedup 1.0000x reference)
#include <cuda_runtime.h>
#include <cuda_fp16.h>
#include <cstdint>

#define NN 100000
#define NE 1600000
#define NG 256
#define SCAN_NB 98   // ceil(100000/1024)
#define NTILES 782   // ceil(100000/128)
#define GEMM_GRID 296

// ---------------- device scratch ----------------
__device__ __half g_xh[(size_t)NN * 128];    // x converted to fp16
__device__ __half g_msg[(size_t)NN * 128];   // xls = isq * (x@W), fp16
__device__ __half g_h[(size_t)NN * 128];     // h (fp16, GEMM input)
__device__ float  g_isq[NN];
__device__ int    g_cnti[NN];
__device__ int    g_fill[NN];
__device__ int    g_rowptr[NN + 1];
__device__ int    g_part[SCAN_NB + 2];
__device__ int    g_offs[SCAN_NB + 2];
__device__ int    g_csr[NE];
__device__ float  g_sums[NG * 64];
__device__ int    g_sync[4];   // [0]=scan arrivals, [1]=offs flag, [2]=rowptr arrivals

// ---------------- helpers ----------------
__device__ __forceinline__ float gelu_tanh(float x) {
    const float c = 0.7978845608028654f;
    float x3 = x * x * x;
    return 0.5f * x * (1.0f + tanhf(c * (x + 0.044715f * x3)));
}

__device__ __forceinline__ __half2 u2h(uint32_t v) { return *reinterpret_cast<__half2*>(&v); }

__device__ __forceinline__ void addcvt(float2& a, uint32_t v) {
    float2 f = __half22float2(u2h(v));
    a.x += f.x; a.y += f.y;
}
__device__ __forceinline__ void addh2(float2& a, __half2 h) {
    float2 f = __half22float2(h);
    a.x += f.x; a.y += f.y;
}

__device__ __forceinline__ void ldsm_x4(uint32_t* r, uint32_t addr) {
    asm volatile("ldmatrix.sync.aligned.m8n8.x4.shared.b16 {%0,%1,%2,%3}, [%4];"
                 : "=r"(r[0]), "=r"(r[1]), "=r"(r[2]), "=r"(r[3]) : "r"(addr));
}
__device__ __forceinline__ void ldsm_x4_t(uint32_t* r, uint32_t addr) {
    asm volatile("ldmatrix.sync.aligned.m8n8.x4.trans.shared.b16 {%0,%1,%2,%3}, [%4];"
                 : "=r"(r[0]), "=r"(r[1]), "=r"(r[2]), "=r"(r[3]) : "r"(addr));
}
__device__ __forceinline__ void mma_f16(float4& d, const uint32_t a[4], uint32_t b0, uint32_t b1) {
    asm volatile(
        "mma.sync.aligned.m16n8k16.row.col.f32.f16.f16.f32 "
        "{%0,%1,%2,%3},{%4,%5,%6,%7},{%8,%9},{%0,%1,%2,%3};"
        : "+f"(d.x), "+f"(d.y), "+f"(d.z), "+f"(d.w)
        : "r"(a[0]), "r"(a[1]), "r"(a[2]), "r"(a[3]), "r"(b0), "r"(b1));
}
__device__ __forceinline__ void cp_commit() { asm volatile("cp.async.commit_group;"); }
template <int N>
__device__ __forceinline__ void cp_wait() { asm volatile("cp.async.wait_group %0;" :: "n"(N)); }

// ---------------- fused x->fp16 convert + degree count ----------------
__global__ void k_prep(const float* __restrict__ x, __half* __restrict__ xh,
                       const int* __restrict__ dst, int* __restrict__ cnt) {
    int i = blockIdx.x * blockDim.x + threadIdx.x;
    if (i < NN * 32) {
        float4 v = __ldg(&((const float4*)x)[i]);
        __half2 h0 = __floats2half2_rn(v.x, v.y);
        __half2 h1 = __floats2half2_rn(v.z, v.w);
        uint2 o; o.x = *(uint32_t*)&h0; o.y = *(uint32_t*)&h1;
        ((uint2*)xh)[i] = o;
    }
    if (i < NE) atomicAdd(&cnt[dst[i]], 1);
}

// ---------------- single-pass scan + isq + rowptr + CSR fill (98 co-resident blocks) ----------------
__global__ __launch_bounds__(1024) void k_scanfill(
    const int* __restrict__ cnt, int* __restrict__ part, int* __restrict__ offs,
    float* __restrict__ isq, int* __restrict__ rowptr, int* __restrict__ sync,
    const int* __restrict__ src, const int* __restrict__ dst,
    int* __restrict__ fill, int* __restrict__ csr) {
    __shared__ int sm[1024];
    __shared__ int is_last;
    int bid = blockIdx.x, t = threadIdx.x;
    int i = bid * 1024 + t;
    int v = (i < NN) ? cnt[i] : 0;
    if (i < NN) isq[i] = rsqrtf((float)v + 1.0f);
    sm[t] = v;
    __syncthreads();
    for (int off = 1; off < 1024; off <<= 1) {
        int tv = (t >= off) ? sm[t - off] : 0;
        __syncthreads();
        sm[t] += tv;
        __syncthreads();
    }
    int incl = sm[t];
    if (t == 1023) part[bid] = incl;
    __syncthreads();
    if (t == 0) {
        __threadfence();
        int old = atomicAdd(&sync[0], 1);
        is_last = (old == SCAN_NB - 1) ? 1 : 0;
    }
    __syncthreads();
    if (is_last) {
        if (t < 128) sm[t] = (t < SCAN_NB) ? part[t] : 0;
        __syncthreads();
        for (int off = 1; off < 128; off <<= 1) {
            int tv = (t >= off && t < 128) ? sm[t - off] : 0;
            __syncthreads();
            if (t < 128) sm[t] += tv;
            __syncthreads();
        }
        if (t < SCAN_NB) offs[t] = (t == 0) ? 0 : sm[t - 1];
        __threadfence();
        __syncthreads();
        if (t == 0) atomicExch(&sync[1], 1);
    }
    if (t == 0) {
        while (*(volatile int*)&sync[1] == 0) { }
    }
    __syncthreads();
    __threadfence();
    int myoff = offs[bid];
    if (i < NN) rowptr[i + 1] = incl + myoff;
    if (i == 0) rowptr[0] = 0;

    // device-wide barrier: rowptr complete
    if (t == 0) {
        __threadfence();
        atomicAdd(&sync[2], 1);
        while (*(volatile int*)&sync[2] < SCAN_NB) { }
    }
    __syncthreads();
    __threadfence();

    // CSR fill (grid-stride over edges)
    for (int e = bid * 1024 + t; e < NE; e += SCAN_NB * 1024) {
        int d = __ldg(&dst[e]);
        int pos = rowptr[d] + atomicAdd(&fill[d], 1);
        csr[pos] = __ldg(&src[e]);
    }
}

// ---------------- pipelined fp16 tensor-core GEMM ----------------
template <int COUT>
__global__ __launch_bounds__(256, 2) void k_gemm_p(
    const __half* __restrict__ X, const float* __restrict__ W,
    const float* __restrict__ s, __half* __restrict__ Y, int n) {
    constexpr int WS = COUT + 8;
    constexpr int NT = COUT / 8;
    constexpr int STAGE = 128 * 136;
    constexpr int CPR = COUT / 8;   // 16B chunks per row
    extern __shared__ __half smh[];
    __half* sW = smh;             // [128][WS]
    __half* sX0 = smh + 128 * WS; // 2 x [128][136]
    int tid = threadIdx.x, lane = tid & 31, warp = tid >> 5;

    uint32_t sx_base = (uint32_t)__cvta_generic_to_shared(sX0);
    uint32_t sw_base = (uint32_t)__cvta_generic_to_shared(sW);

    auto load_tile = [&](int tile, int stage) {
        int row0 = tile * 128;
        uint32_t sb = sx_base + (uint32_t)(stage * STAGE * 2);
        #pragma unroll
        for (int i = tid; i < 128 * 16; i += 256) {
            int r = i >> 4, c = i & 15;
            int gr = row0 + r;
            if (gr < n)
                asm volatile("cp.async.cg.shared.global [%0], [%1], 16;"
                             :: "r"(sb + (uint32_t)(r * 272 + c * 16)),
                                "l"(X + (size_t)gr * 128 + c * 8));
        }
        cp_commit();
    };

    const int G = gridDim.x;
    int t0 = blockIdx.x;
    if (t0 < NTILES) load_tile(t0, 0);

    // stage W once (fp32 -> fp16)
    for (int i = tid; i < 128 * (COUT / 4); i += 256) {
        int k = i / (COUT / 4), c4 = (i % (COUT / 4)) * 4;
        float4 wv = __ldg(&((const float4*)W)[i]);
        __half2 h0 = __floats2half2_rn(wv.x, wv.y);
        __half2 h1 = __floats2half2_rn(wv.z, wv.w);
        uint2 o; o.x = *(uint32_t*)&h0; o.y = *(uint32_t*)&h1;
        *(uint2*)&sW[k * WS + c4] = o;
    }

    int stage = 0;
    int lane15 = lane & 15, laneh = (lane >> 4) << 3;
    int rw = warp * 16;

    for (int t = t0; t < NTILES; t += G) {
        int tn = t + G;
        if (tn < NTILES) { load_tile(tn, stage ^ 1); cp_wait<1>(); }
        else             { cp_wait<0>(); }
        __syncthreads();

        float4 acc[NT];
        #pragma unroll
        for (int q = 0; q < NT; q++) acc[q] = make_float4(0.f, 0.f, 0.f, 0.f);

        uint32_t sxs = sx_base + (uint32_t)(stage * STAGE * 2);
        __half* sXp = sX0 + stage * STAGE;
        #pragma unroll
        for (int kt = 0; kt < 8; kt++) {
            uint32_t afr[4];
            ldsm_x4(afr, sxs + (uint32_t)(((rw + lane15) * 136 + kt * 16 + laneh) * 2));
            #pragma unroll
            for (int np = 0; np < NT / 2; np++) {
                uint32_t bfr[4];
                ldsm_x4_t(bfr, sw_base + (uint32_t)(((kt * 16 + lane15) * WS + np * 16 + laneh) * 2));
                mma_f16(acc[2 * np], afr, bfr[0], bfr[1]);
                mma_f16(acc[2 * np + 1], afr, bfr[2], bfr[3]);
            }
        }

        // epilogue: scale, stage in consumed smem, coalesced 16B stores
        int qid = lane >> 2, tq = lane & 3;
        int row0 = t * 128;
        int r1 = row0 + rw + qid, r2 = r1 + 8;
        float s1v = (r1 < n) ? __ldg(&s[r1]) : 0.f;
        float s2v = (r2 < n) ? __ldg(&s[r2]) : 0.f;
        #pragma unroll
        for (int nt = 0; nt < NT; nt++) {
            int c = nt * 8 + 2 * tq;
            *(__half2*)&sXp[(rw + qid) * 136 + c]     = __floats2half2_rn(s1v * acc[nt].x, s1v * acc[nt].y);
            *(__half2*)&sXp[(rw + qid + 8) * 136 + c] = __floats2half2_rn(s2v * acc[nt].z, s2v * acc[nt].w);
        }
        __syncwarp();
        #pragma unroll
        for (int q = 0; q < 16 * CPR / 32; q++) {
            int idx = q * 32 + lane;
            int r = idx / CPR, c = idx % CPR;
            int gr = row0 + rw + r;
            if (gr < n)
                *(uint4*)&Y[(size_t)gr * COUT + c * 8] = *(uint4*)&sXp[(rw + r) * 136 + c * 8];
        }
        __syncthreads();
        stage ^= 1;
    }
}

// ---------------- edge gather: half-warp per edge, depth-3 fp16 tree ----------------
// h[i] = gelu( isq[i] * (sum_{j in N(i)} msg[j] + msg[i]) + b )
__global__ __launch_bounds__(256) void k_edgenode128(
    const int* __restrict__ rp, const int* __restrict__ csr,
    const float* __restrict__ isq, const __half* __restrict__ msg,
    const float* __restrict__ b, __half* __restrict__ h) {
    int w = (blockIdx.x * blockDim.x + threadIdx.x) >> 5;
    int lane = threadIdx.x & 31;
    if (w >= NN) return;
    int hw = lane >> 4, l16 = lane & 15;
    int e0 = __ldg(&rp[w]), e1 = __ldg(&rp[w + 1]);
    const uint4* M4 = (const uint4*)msg;   // 8 halves per lane-chunk, 16 chunks/row
    float2 a0 = {0.f, 0.f}, a1 = {0.f, 0.f}, a2 = {0.f, 0.f}, a3 = {0.f, 0.f};

    for (int base = e0; base < e1; base += 32) {
        int n = e1 - base; if (n > 32) n = 32;
        int myidx = 0;
        if (lane < n) myidx = __ldg(&csr[base + lane]);
        int j = 0;
        for (; j + 16 <= n; j += 16) {
            int ss[8]; uint4 vv[8];
            #pragma unroll
            for (int q = 0; q < 8; q++) ss[q] = __shfl_sync(0xffffffffu, myidx, j + 2 * q + hw);
            #pragma unroll
            for (int q = 0; q < 8; q++) vv[q] = __ldg(&M4[(size_t)ss[q] * 16 + l16]);
            __half2 tx = __hadd2(__hadd2(__hadd2(u2h(vv[0].x), u2h(vv[1].x)), __hadd2(u2h(vv[2].x), u2h(vv[3].x))),
                                 __hadd2(__hadd2(u2h(vv[4].x), u2h(vv[5].x)), __hadd2(u2h(vv[6].x), u2h(vv[7].x))));
            __half2 ty = __hadd2(__hadd2(__hadd2(u2h(vv[0].y), u2h(vv[1].y)), __hadd2(u2h(vv[2].y), u2h(vv[3].y))),
                                 __hadd2(__hadd2(u2h(vv[4].y), u2h(vv[5].y)), __hadd2(u2h(vv[6].y), u2h(vv[7].y))));
            __half2 tz = __hadd2(__hadd2(__hadd2(u2h(vv[0].z), u2h(vv[1].z)), __hadd2(u2h(vv[2].z), u2h(vv[3].z))),
                                 __hadd2(__hadd2(u2h(vv[4].z), u2h(vv[5].z)), __hadd2(u2h(vv[6].z), u2h(vv[7].z))));
            __half2 tw = __hadd2(__hadd2(__hadd2(u2h(vv[0].w), u2h(vv[1].w)), __hadd2(u2h(vv[2].w), u2h(vv[3].w))),
                                 __hadd2(__hadd2(u2h(vv[4].w), u2h(vv[5].w)), __hadd2(u2h(vv[6].w), u2h(vv[7].w))));
            addh2(a0, tx); addh2(a1, ty); addh2(a2, tz); addh2(a3, tw);
        }
        if (j + 8 <= n) {
            int ss[4]; uint4 vv[4];
            #pragma unroll
            for (int q = 0; q < 4; q++) ss[q] = __shfl_sync(0xffffffffu, myidx, j + 2 * q + hw);
            #pragma unroll
            for (int q = 0; q < 4; q++) vv[q] = __ldg(&M4[(size_t)ss[q] * 16 + l16]);
            addh2(a0, __hadd2(__hadd2(u2h(vv[0].x), u2h(vv[1].x)), __hadd2(u2h(vv[2].x), u2h(vv[3].x))));
            addh2(a1, __hadd2(__hadd2(u2h(vv[0].y), u2h(vv[1].y)), __hadd2(u2h(vv[2].y), u2h(vv[3].y))));
            addh2(a2, __hadd2(__hadd2(u2h(vv[0].z), u2h(vv[1].z)), __hadd2(u2h(vv[2].z), u2h(vv[3].z))));
            addh2(a3, __hadd2(__hadd2(u2h(vv[0].w), u2h(vv[1].w)), __hadd2(u2h(vv[2].w), u2h(vv[3].w))));
            j += 8;
        }
        if (j + 4 <= n) {
            int ss[2]; uint4 vv[2];
            #pragma unroll
            for (int q = 0; q < 2; q++) ss[q] = __shfl_sync(0xffffffffu, myidx, j + 2 * q + hw);
            #pragma unroll
            for (int q = 0; q < 2; q++) vv[q] = __ldg(&M4[(size_t)ss[q] * 16 + l16]);
            addh2(a0, __hadd2(u2h(vv[0].x), u2h(vv[1].x)));
            addh2(a1, __hadd2(u2h(vv[0].y), u2h(vv[1].y)));
            addh2(a2, __hadd2(u2h(vv[0].z), u2h(vv[1].z)));
            addh2(a3, __hadd2(u2h(vv[0].w), u2h(vv[1].w)));
            j += 4;
        }
        for (; j < n; j += 2) {
            int jj = j + hw;
            bool valid = jj < n;
            int s0 = __shfl_sync(0xffffffffu, myidx, valid ? jj : j);
            uint4 v = __ldg(&M4[(size_t)s0 * 16 + l16]);
            if (valid) { addcvt(a0, v.x); addcvt(a1, v.y); addcvt(a2, v.z); addcvt(a3, v.w); }
        }
    }

    // cross-half reduction (lanes l and l+16 hold same feature cols)
    a0.x += __shfl_xor_sync(0xffffffffu, a0.x, 16);
    a0.y += __shfl_xor_sync(0xffffffffu, a0.y, 16);
    a1.x += __shfl_xor_sync(0xffffffffu, a1.x, 16);
    a1.y += __shfl_xor_sync(0xffffffffu, a1.y, 16);
    a2.x += __shfl_xor_sync(0xffffffffu, a2.x, 16);
    a2.y += __shfl_xor_sync(0xffffffffu, a2.y, 16);
    a3.x += __shfl_xor_sync(0xffffffffu, a3.x, 16);
    a3.y += __shfl_xor_sync(0xffffffffu, a3.y, 16);

    if (hw == 0) {
        uint4 sv = __ldg(&M4[(size_t)w * 16 + l16]);   // self
        addcvt(a0, sv.x); addcvt(a1, sv.y); addcvt(a2, sv.z); addcvt(a3, sv.w);
        float sc = __ldg(&isq[w]);
        float4 bb0 = __ldg(&((const float4*)b)[l16 * 2]);
        float4 bb1 = __ldg(&((const float4*)b)[l16 * 2 + 1]);
        __half2 p0 = __floats2half2_rn(gelu_tanh(sc * a0.x + bb0.x), gelu_tanh(sc * a0.y + bb0.y));
        __half2 p1 = __floats2half2_rn(gelu_tanh(sc * a1.x + bb0.z), gelu_tanh(sc * a1.y + bb0.w));
        __half2 p2 = __floats2half2_rn(gelu_tanh(sc * a2.x + bb1.x), gelu_tanh(sc * a2.y + bb1.y));
        __half2 p3 = __floats2half2_rn(gelu_tanh(sc * a3.x + bb1.z), gelu_tanh(sc * a3.y + bb1.w));
        uint4 o;
        o.x = *(uint32_t*)&p0; o.y = *(uint32_t*)&p1;
        o.z = *(uint32_t*)&p2; o.w = *(uint32_t*)&p3;
        ((uint4*)h)[(size_t)w * 16 + l16] = o;
    }
}

// final layer: quarter-warp per edge (COUT=64) + gelu + fused mean-pool reduction
__global__ __launch_bounds__(256) void k_edgepool(
    const int* __restrict__ rp, const int* __restrict__ csr,
    const float* __restrict__ isq, const __half* __restrict__ msg,
    const float* __restrict__ b, const int* __restrict__ batch,
    float* __restrict__ sums) {
    int w = (blockIdx.x * blockDim.x + threadIdx.x) >> 5;
    int lane = threadIdx.x & 31;
    if (w >= NN) return;
    int qw = lane >> 3, l8 = lane & 7;
    int e0 = __ldg(&rp[w]), e1 = __ldg(&rp[w + 1]);
    const uint4* M4 = (const uint4*)msg;   // 8 chunks/row (64 halves)
    float2 a0 = {0.f, 0.f}, a1 = {0.f, 0.f}, a2 = {0.f, 0.f}, a3 = {0.f, 0.f};

    for (int base = e0; base < e1; base += 32) {
        int n = e1 - base; if (n > 32) n = 32;
        int myidx = 0;
        if (lane < n) myidx = __ldg(&csr[base + lane]);
        int j = 0;
        for (; j + 16 <= n; j += 16) {
            int ss[4]; uint4 vv[4];
            #pragma unroll
            for (int q = 0; q < 4; q++) ss[q] = __shfl_sync(0xffffffffu, myidx, j + 4 * q + qw);
            #pragma unroll
            for (int q = 0; q < 4; q++) vv[q] = __ldg(&M4[(size_t)ss[q] * 8 + l8]);
            addh2(a0, __hadd2(__hadd2(u2h(vv[0].x), u2h(vv[1].x)), __hadd2(u2h(vv[2].x), u2h(vv[3].x))));
            addh2(a1, __hadd2(__hadd2(u2h(vv[0].y), u2h(vv[1].y)), __hadd2(u2h(vv[2].y), u2h(vv[3].y))));
            addh2(a2, __hadd2(__hadd2(u2h(vv[0].z), u2h(vv[1].z)), __hadd2(u2h(vv[2].z), u2h(vv[3].z))));
            addh2(a3, __hadd2(__hadd2(u2h(vv[0].w), u2h(vv[1].w)), __hadd2(u2h(vv[2].w), u2h(vv[3].w))));
        }
        if (j + 8 <= n) {
            int ss[2]; uint4 vv[2];
            #pragma unroll
            for (int q = 0; q < 2; q++) ss[q] = __shfl_sync(0xffffffffu, myidx, j + 4 * q + qw);
            #pragma unroll
            for (int q = 0; q < 2; q++) vv[q] = __ldg(&M4[(size_t)ss[q] * 8 + l8]);
            addh2(a0, __hadd2(u2h(vv[0].x), u2h(vv[1].x)));
            addh2(a1, __hadd2(u2h(vv[0].y), u2h(vv[1].y)));
            addh2(a2, __hadd2(u2h(vv[0].z), u2h(vv[1].z)));
            addh2(a3, __hadd2(u2h(vv[0].w), u2h(vv[1].w)));
            j += 8;
        }
        for (; j < n; j += 4) {
            int jj = j + qw;
            bool valid = jj < n;
            int s0 = __shfl_sync(0xffffffffu, myidx, valid ? jj : j);
            uint4 v = __ldg(&M4[(size_t)s0 * 8 + l8]);
            if (valid) { addcvt(a0, v.x); addcvt(a1, v.y); addcvt(a2, v.z); addcvt(a3, v.w); }
        }
    }

    // cross-quarter reduction (xor 8, then xor 16)
    #pragma unroll
    for (int d = 8; d <= 16; d <<= 1) {
        a0.x += __shfl_xor_sync(0xffffffffu, a0.x, d);
        a0.y += __shfl_xor_sync(0xffffffffu, a0.y, d);
        a1.x += __shfl_xor_sync(0xffffffffu, a1.x, d);
        a1.y += __shfl_xor_sync(0xffffffffu, a1.y, d);
        a2.x += __shfl_xor_sync(0xffffffffu, a2.x, d);
        a2.y += __shfl_xor_sync(0xffffffffu, a2.y, d);
        a3.x += __shfl_xor_sync(0xffffffffu, a3.x, d);
        a3.y += __shfl_xor_sync(0xffffffffu, a3.y, d);
    }

    if (lane < 8) {
        uint4 sv = __ldg(&M4[(size_t)w * 8 + l8]);   // self
        addcvt(a0, sv.x); addcvt(a1, sv.y); addcvt(a2, sv.z); addcvt(a3, sv.w);
        float sc = __ldg(&isq[w]);
        float4 bb0 = __ldg(&((const float4*)b)[l8 * 2]);
        float4 bb1 = __ldg(&((const float4*)b)[l8 * 2 + 1]);
        float g0 = gelu_tanh(sc * a0.x + bb0.x), g1 = gelu_tanh(sc * a0.y + bb0.y);
        float g2 = gelu_tanh(sc * a1.x + bb0.z), g3 = gelu_tanh(sc * a1.y + bb0.w);
        float g4 = gelu_tanh(sc * a2.x + bb1.x), g5 = gelu_tanh(sc * a2.y + bb1.y);
        float g6 = gelu_tanh(sc * a3.x + bb1.z), g7 = gelu_tanh(sc * a3.y + bb1.w);
        int g = __ldg(&batch[w]);
        float* p = sums + (size_t)g * 64 + (size_t)l8 * 8;
        asm volatile("red.global.add.v4.f32 [%0], {%1,%2,%3,%4};"
                     :: "l"(p), "f"(g0), "f"(g1), "f"(g2), "f"(g3) : "memory");
        asm volatile("red.global.add.v4.f32 [%0], {%1,%2,%3,%4};"
                     :: "l"(p + 4), "f"(g4), "f"(g5), "f"(g6), "f"(g7) : "memory");
    }
}

// ---------------- pool finalize (counts via binary search, per-thread) ----------------
__global__ void k_pool_fin(const float* __restrict__ sums, const int* __restrict__ batch,
                           float* __restrict__ out) {
    int i = blockIdx.x * blockDim.x + threadIdx.x;
    if (i >= NG * 64) return;
    int g = i >> 6;
    int lo = 0, hi = NN;
    while (lo < hi) { int mid = (lo + hi) >> 1; if (__ldg(&batch[mid]) < g) lo = mid + 1; else hi = mid; }
    int a = lo;
    lo = 0; hi = NN;
    while (lo < hi) { int mid = (lo + hi) >> 1; if (__ldg(&batch[mid]) < g + 1) lo = mid + 1; else hi = mid; }
    float c = fmaxf((float)(lo - a), 1.0f);
    out[i] = sums[i] / c;
}

// ---------------- launch ----------------
extern "C" void kernel_launch(void* const* d_in, const int* in_sizes, int n_in,
                              void* d_out, int out_size) {
    const float* x = (const float*)d_in[0];
    const int* ei = (const int*)d_in[1];
    const int* batch = (const int*)d_in[2];
    const float* W0 = (const float*)d_in[3];
    const float* b0 = (const float*)d_in[4];
    const float* W1 = (const float*)d_in[5];
    const float* b1 = (const float*)d_in[6];
    const float* W2 = (const float*)d_in[7];
    const float* b2 = (const float*)d_in[8];
    const int* src = ei;
    const int* dst = ei + NE;

    __half *xh, *msg, *hbuf;
    float *isq, *sums;
    int *cnti, *fill, *rowptr, *part, *offs, *csr, *sync;
    cudaGetSymbolAddress((void**)&xh, g_xh);
    cudaGetSymbolAddress((void**)&msg, g_msg);
    cudaGetSymbolAddress((void**)&hbuf, g_h);
    cudaGetSymbolAddress((void**)&isq, g_isq);
    cudaGetSymbolAddress((void**)&cnti, g_cnti);
    cudaGetSymbolAddress((void**)&fill, g_fill);
    cudaGetSymbolAddress((void**)&rowptr, g_rowptr);
    cudaGetSymbolAddress((void**)&part, g_part);
    cudaGetSymbolAddress((void**)&offs, g_offs);
    cudaGetSymbolAddress((void**)&csr, g_csr);
    cudaGetSymbolAddress((void**)&sums, g_sums);
    cudaGetSymbolAddress((void**)&sync, g_sync);

    const int SM128 = (128 * 136 + 2 * 128 * 136) * 2;  // 104448
    const int SM64  = (128 * 72 + 2 * 128 * 136) * 2;   // 88064
    cudaFuncSetAttribute(k_gemm_p<128>, cudaFuncAttributeMaxDynamicSharedMemorySize, SM128);
    cudaFuncSetAttribute(k_gemm_p<64>, cudaFuncAttributeMaxDynamicSharedMemorySize, SM64);

    // memsets (not kernel launches)
    cudaMemsetAsync(cnti, 0, NN * sizeof(int));
    cudaMemsetAsync(fill, 0, NN * sizeof(int));
    cudaMemsetAsync(sums, 0, NG * 64 * sizeof(float));
    cudaMemsetAsync(sync, 0, 4 * sizeof(int));

    // kernel launches — single stream; k_edgenode128 at index 3 for ncu capture
    k_prep<<<(NN * 32 + 255) / 256, 256>>>(x, xh, dst, cnti);                    // 0
    k_scanfill<<<SCAN_NB, 1024>>>(cnti, part, offs, isq, rowptr, sync,
                                  src, dst, fill, csr);                          // 1
    k_gemm_p<128><<<GEMM_GRID, 256, SM128>>>(xh, W0, isq, msg, NN);              // 2
    k_edgenode128<<<(NN * 32 + 255) / 256, 256>>>(rowptr, csr, isq, msg, b0, hbuf); // 3 <- profiled
    k_gemm_p<128><<<GEMM_GRID, 256, SM128>>>(hbuf, W1, isq, msg, NN);            // 4
    k_edgenode128<<<(NN * 32 + 255) / 256, 256>>>(rowptr, csr, isq, msg, b1, hbuf); // 5
    k_gemm_p<64><<<GEMM_GRID, 256, SM64>>>(hbuf, W2, isq, msg, NN);              // 6
    k_edgepool<<<(NN * 32 + 255) / 256, 256>>>(rowptr, csr, isq, msg, b2, batch, sums); // 7
    k_pool_fin<<<(NG * 64 + 255) / 256, 256>>>(sums, batch, (float*)d_out);      // 8
}

// round 14
// speedup vs baseline: 1.2795x; 1.2795x over previous
#include <cuda_runtime.h>
#include <cuda_fp16.h>
#include <cstdint>

#define NN 100000
#define NE 1600000
#define NG 256
#define SCAN_NB 98   // ceil(100000/1024)
#define NTILES 782   // ceil(100000/128)
#define GEMM_GRID 296

// ---------------- device scratch ----------------
__device__ __half g_xh[(size_t)NN * 128];    // x converted to fp16
__device__ __half g_msg[(size_t)NN * 128];   // xls = isq * (x@W), fp16
__device__ __half g_h[(size_t)NN * 128];     // h (fp16, GEMM input)
__device__ float  g_isq[NN];
__device__ int    g_cnti[NN];
__device__ int    g_fill[NN];
__device__ int    g_rowptr[NN + 1];
__device__ int    g_part[SCAN_NB + 2];
__device__ int    g_offs[SCAN_NB + 2];
__device__ int    g_csr[NE];
__device__ float  g_sums[NG * 64];
__device__ int    g_sync[4];

// ---------------- helpers ----------------
__device__ __forceinline__ float gelu_tanh(float x) {
    const float c = 0.7978845608028654f;
    float x3 = x * x * x;
    return 0.5f * x * (1.0f + tanhf(c * (x + 0.044715f * x3)));
}

__device__ __forceinline__ __half2 u2h(uint32_t v) { return *reinterpret_cast<__half2*>(&v); }

__device__ __forceinline__ void acc_h2x2(float4& acc, uint2 v) {
    float2 lo = __half22float2(u2h(v.x));
    float2 hi = __half22float2(u2h(v.y));
    acc.x += lo.x; acc.y += lo.y; acc.z += hi.x; acc.w += hi.y;
}

__device__ __forceinline__ void ldsm_x4(uint32_t* r, uint32_t addr) {
    asm volatile("ldmatrix.sync.aligned.m8n8.x4.shared.b16 {%0,%1,%2,%3}, [%4];"
                 : "=r"(r[0]), "=r"(r[1]), "=r"(r[2]), "=r"(r[3]) : "r"(addr));
}
__device__ __forceinline__ void ldsm_x4_t(uint32_t* r, uint32_t addr) {
    asm volatile("ldmatrix.sync.aligned.m8n8.x4.trans.shared.b16 {%0,%1,%2,%3}, [%4];"
                 : "=r"(r[0]), "=r"(r[1]), "=r"(r[2]), "=r"(r[3]) : "r"(addr));
}
__device__ __forceinline__ void mma_f16(float4& d, const uint32_t a[4], uint32_t b0, uint32_t b1) {
    asm volatile(
        "mma.sync.aligned.m16n8k16.row.col.f32.f16.f16.f32 "
        "{%0,%1,%2,%3},{%4,%5,%6,%7},{%8,%9},{%0,%1,%2,%3};"
        : "+f"(d.x), "+f"(d.y), "+f"(d.z), "+f"(d.w)
        : "r"(a[0]), "r"(a[1]), "r"(a[2]), "r"(a[3]), "r"(b0), "r"(b1));
}
__device__ __forceinline__ void cp_commit() { asm volatile("cp.async.commit_group;"); }
template <int N>
__device__ __forceinline__ void cp_wait() { asm volatile("cp.async.wait_group %0;" :: "n"(N)); }

// ---------------- fused x->fp16 convert + degree count ----------------
__global__ void k_prep(const float* __restrict__ x, __half* __restrict__ xh,
                       const int* __restrict__ dst, int* __restrict__ cnt) {
    int i = blockIdx.x * blockDim.x + threadIdx.x;
    if (i < NN * 32) {
        float4 v = __ldg(&((const float4*)x)[i]);
        __half2 h0 = __floats2half2_rn(v.x, v.y);
        __half2 h1 = __floats2half2_rn(v.z, v.w);
        uint2 o; o.x = *(uint32_t*)&h0; o.y = *(uint32_t*)&h1;
        ((uint2*)xh)[i] = o;
    }
    if (i < NE) atomicAdd(&cnt[dst[i]], 1);
}

// ---------------- single-pass scan + isq + rowptr + CSR fill (98 co-resident blocks) ----------------
__global__ __launch_bounds__(1024) void k_scanfill(
    const int* __restrict__ cnt, int* __restrict__ part, int* __restrict__ offs,
    float* __restrict__ isq, int* __restrict__ rowptr, int* __restrict__ sync,
    const int* __restrict__ src, const int* __restrict__ dst,
    int* __restrict__ fill, int* __restrict__ csr) {
    __shared__ int sm[1024];
    __shared__ int is_last;
    int bid = blockIdx.x, t = threadIdx.x;
    int i = bid * 1024 + t;
    int v = (i < NN) ? cnt[i] : 0;
    if (i < NN) isq[i] = rsqrtf((float)v + 1.0f);
    sm[t] = v;
    __syncthreads();
    for (int off = 1; off < 1024; off <<= 1) {
        int tv = (t >= off) ? sm[t - off] : 0;
        __syncthreads();
        sm[t] += tv;
        __syncthreads();
    }
    int incl = sm[t];
    if (t == 1023) part[bid] = incl;
    __syncthreads();
    if (t == 0) {
        __threadfence();
        int old = atomicAdd(&sync[0], 1);
        is_last = (old == SCAN_NB - 1) ? 1 : 0;
    }
    __syncthreads();
    if (is_last) {
        if (t < 128) sm[t] = (t < SCAN_NB) ? part[t] : 0;
        __syncthreads();
        for (int off = 1; off < 128; off <<= 1) {
            int tv = (t >= off && t < 128) ? sm[t - off] : 0;
            __syncthreads();
            if (t < 128) sm[t] += tv;
            __syncthreads();
        }
        if (t < SCAN_NB) offs[t] = (t == 0) ? 0 : sm[t - 1];
        __threadfence();
        __syncthreads();
        if (t == 0) atomicExch(&sync[1], 1);
    }
    if (t == 0) {
        while (*(volatile int*)&sync[1] == 0) { }
    }
    __syncthreads();
    __threadfence();
    int myoff = offs[bid];
    if (i < NN) rowptr[i + 1] = incl + myoff;
    if (i == 0) rowptr[0] = 0;

    if (t == 0) {
        __threadfence();
        atomicAdd(&sync[2], 1);
        while (*(volatile int*)&sync[2] < SCAN_NB) { }
    }
    __syncthreads();
    __threadfence();

    for (int e = bid * 1024 + t; e < NE; e += SCAN_NB * 1024) {
        int d = __ldg(&dst[e]);
        int pos = rowptr[d] + atomicAdd(&fill[d], 1);
        csr[pos] = __ldg(&src[e]);
    }
}

// ---------------- pipelined fp16 tensor-core GEMM ----------------
template <int COUT>
__global__ __launch_bounds__(256, 2) void k_gemm_p(
    const __half* __restrict__ X, const float* __restrict__ W,
    const float* __restrict__ s, __half* __restrict__ Y, int n) {
    constexpr int WS = COUT + 8;
    constexpr int NT = COUT / 8;
    constexpr int STAGE = 128 * 136;
    constexpr int CPR = COUT / 8;
    extern __shared__ __half smh[];
    __half* sW = smh;             // [128][WS]
    __half* sX0 = smh + 128 * WS; // 2 x [128][136]
    int tid = threadIdx.x, lane = tid & 31, warp = tid >> 5;

    uint32_t sx_base = (uint32_t)__cvta_generic_to_shared(sX0);
    uint32_t sw_base = (uint32_t)__cvta_generic_to_shared(sW);

    auto load_tile = [&](int tile, int stage) {
        int row0 = tile * 128;
        uint32_t sb = sx_base + (uint32_t)(stage * STAGE * 2);
        #pragma unroll
        for (int i = tid; i < 128 * 16; i += 256) {
            int r = i >> 4, c = i & 15;
            int gr = row0 + r;
            if (gr < n)
                asm volatile("cp.async.cg.shared.global [%0], [%1], 16;"
                             :: "r"(sb + (uint32_t)(r * 272 + c * 16)),
                                "l"(X + (size_t)gr * 128 + c * 8));
        }
        cp_commit();
    };

    const int G = gridDim.x;
    int t0 = blockIdx.x;
    if (t0 < NTILES) load_tile(t0, 0);

    for (int i = tid; i < 128 * (COUT / 4); i += 256) {
        int k = i / (COUT / 4), c4 = (i % (COUT / 4)) * 4;
        float4 wv = __ldg(&((const float4*)W)[i]);
        __half2 h0 = __floats2half2_rn(wv.x, wv.y);
        __half2 h1 = __floats2half2_rn(wv.z, wv.w);
        uint2 o; o.x = *(uint32_t*)&h0; o.y = *(uint32_t*)&h1;
        *(uint2*)&sW[k * WS + c4] = o;
    }

    int stage = 0;
    int lane15 = lane & 15, laneh = (lane >> 4) << 3;
    int rw = warp * 16;

    for (int t = t0; t < NTILES; t += G) {
        int tn = t + G;
        if (tn < NTILES) { load_tile(tn, stage ^ 1); cp_wait<1>(); }
        else             { cp_wait<0>(); }
        __syncthreads();

        float4 acc[NT];
        #pragma unroll
        for (int q = 0; q < NT; q++) acc[q] = make_float4(0.f, 0.f, 0.f, 0.f);

        uint32_t sxs = sx_base + (uint32_t)(stage * STAGE * 2);
        __half* sXp = sX0 + stage * STAGE;
        #pragma unroll
        for (int kt = 0; kt < 8; kt++) {
            uint32_t afr[4];
            ldsm_x4(afr, sxs + (uint32_t)(((rw + lane15) * 136 + kt * 16 + laneh) * 2));
            #pragma unroll
            for (int np = 0; np < NT / 2; np++) {
                uint32_t bfr[4];
                ldsm_x4_t(bfr, sw_base + (uint32_t)(((kt * 16 + lane15) * WS + np * 16 + laneh) * 2));
                mma_f16(acc[2 * np], afr, bfr[0], bfr[1]);
                mma_f16(acc[2 * np + 1], afr, bfr[2], bfr[3]);
            }
        }

        int qid = lane >> 2, tq = lane & 3;
        int row0 = t * 128;
        int r1 = row0 + rw + qid, r2 = r1 + 8;
        float s1v = (r1 < n) ? __ldg(&s[r1]) : 0.f;
        float s2v = (r2 < n) ? __ldg(&s[r2]) : 0.f;
        #pragma unroll
        for (int nt = 0; nt < NT; nt++) {
            int c = nt * 8 + 2 * tq;
            *(__half2*)&sXp[(rw + qid) * 136 + c]     = __floats2half2_rn(s1v * acc[nt].x, s1v * acc[nt].y);
            *(__half2*)&sXp[(rw + qid + 8) * 136 + c] = __floats2half2_rn(s2v * acc[nt].z, s2v * acc[nt].w);
        }
        __syncwarp();
        #pragma unroll
        for (int q = 0; q < 16 * CPR / 32; q++) {
            int idx = q * 32 + lane;
            int r = idx / CPR, c = idx % CPR;
            int gr = row0 + rw + r;
            if (gr < n)
                *(uint4*)&Y[(size_t)gr * COUT + c * 8] = *(uint4*)&sXp[(rw + r) * 136 + c * 8];
        }
        __syncthreads();
        stage ^= 1;
    }
}

// ---------------- fused edge gather + node epilogue (uint2/lane, depth-3 fp16 tree) ----------------
// h[i] = gelu( isq[i] * (sum_{j in N(i)} msg[j] + msg[i]) + b )   (h fp16)
__global__ __launch_bounds__(256) void k_edgenode128(
    const int* __restrict__ rp, const int* __restrict__ csr,
    const float* __restrict__ isq, const __half* __restrict__ msg,
    const float* __restrict__ b, __half* __restrict__ h) {
    int w = (blockIdx.x * blockDim.x + threadIdx.x) >> 5;
    int lane = threadIdx.x & 31;
    if (w >= NN) return;
    int e0 = __ldg(&rp[w]), e1 = __ldg(&rp[w + 1]);
    const uint2* M = (const uint2*)msg;
    float4 acc = make_float4(0.f, 0.f, 0.f, 0.f);
    acc_h2x2(acc, __ldg(&M[(size_t)w * 32 + lane]));   // self

    for (int base = e0; base < e1; base += 32) {
        int n = e1 - base; if (n > 32) n = 32;
        int myidx = 0;
        if (lane < n) myidx = __ldg(&csr[base + lane]);
        int j = 0;
        for (; j + 8 <= n; j += 8) {
            int ss[8]; uint2 vv[8];
            #pragma unroll
            for (int q = 0; q < 8; q++) ss[q] = __shfl_sync(0xffffffffu, myidx, j + q);
            #pragma unroll
            for (int q = 0; q < 8; q++) vv[q] = __ldg(&M[(size_t)ss[q] * 32 + lane]);
            // depth-3 fp16 tree over all 8 edges, then one fp32 accumulate
            __half2 px = __hadd2(
                __hadd2(__hadd2(u2h(vv[0].x), u2h(vv[1].x)), __hadd2(u2h(vv[2].x), u2h(vv[3].x))),
                __hadd2(__hadd2(u2h(vv[4].x), u2h(vv[5].x)), __hadd2(u2h(vv[6].x), u2h(vv[7].x))));
            __half2 py = __hadd2(
                __hadd2(__hadd2(u2h(vv[0].y), u2h(vv[1].y)), __hadd2(u2h(vv[2].y), u2h(vv[3].y))),
                __hadd2(__hadd2(u2h(vv[4].y), u2h(vv[5].y)), __hadd2(u2h(vv[6].y), u2h(vv[7].y))));
            float2 fx = __half22float2(px);
            float2 fy = __half22float2(py);
            acc.x += fx.x; acc.y += fx.y; acc.z += fy.x; acc.w += fy.y;
        }
        if (j + 4 <= n) {
            int ss[4]; uint2 vv[4];
            #pragma unroll
            for (int q = 0; q < 4; q++) ss[q] = __shfl_sync(0xffffffffu, myidx, j + q);
            #pragma unroll
            for (int q = 0; q < 4; q++) vv[q] = __ldg(&M[(size_t)ss[q] * 32 + lane]);
            __half2 px = __hadd2(__hadd2(u2h(vv[0].x), u2h(vv[1].x)),
                                 __hadd2(u2h(vv[2].x), u2h(vv[3].x)));
            __half2 py = __hadd2(__hadd2(u2h(vv[0].y), u2h(vv[1].y)),
                                 __hadd2(u2h(vv[2].y), u2h(vv[3].y)));
            float2 fx = __half22float2(px);
            float2 fy = __half22float2(py);
            acc.x += fx.x; acc.y += fx.y; acc.z += fy.x; acc.w += fy.y;
            j += 4;
        }
        for (; j < n; j++) {
            int s0 = __shfl_sync(0xffffffffu, myidx, j);
            acc_h2x2(acc, __ldg(&M[(size_t)s0 * 32 + lane]));
        }
    }
    float sc = __ldg(&isq[w]);
    float4 bb = __ldg(&((const float4*)b)[lane]);
    __half2 p0 = __floats2half2_rn(gelu_tanh(sc * acc.x + bb.x), gelu_tanh(sc * acc.y + bb.y));
    __half2 p1 = __floats2half2_rn(gelu_tanh(sc * acc.z + bb.z), gelu_tanh(sc * acc.w + bb.w));
    uint2 out; out.x = *(uint32_t*)&p0; out.y = *(uint32_t*)&p1;
    ((uint2*)h)[(size_t)w * 32 + lane] = out;
}

// final layer: gather (COUT=64) + gelu + fused mean-pool reduction into sums
__global__ __launch_bounds__(256) void k_edgepool(
    const int* __restrict__ rp, const int* __restrict__ csr,
    const float* __restrict__ isq, const __half* __restrict__ msg,
    const float* __restrict__ b, const int* __restrict__ batch,
    float* __restrict__ sums) {
    int w = (blockIdx.x * blockDim.x + threadIdx.x) >> 5;
    int lane = threadIdx.x & 31;
    if (w >= NN) return;
    int e0 = __ldg(&rp[w]), e1 = __ldg(&rp[w + 1]);
    const uint32_t* M = (const uint32_t*)msg;
    float2 acc;
    {
        acc = __half22float2(u2h(__ldg(&M[(size_t)w * 32 + lane])));
    }
    for (int base = e0; base < e1; base += 32) {
        int n = e1 - base; if (n > 32) n = 32;
        int myidx = 0;
        if (lane < n) myidx = __ldg(&csr[base + lane]);
        int j = 0;
        for (; j + 8 <= n; j += 8) {
            int ss[8]; uint32_t vv[8];
            #pragma unroll
            for (int q = 0; q < 8; q++) ss[q] = __shfl_sync(0xffffffffu, myidx, j + q);
            #pragma unroll
            for (int q = 0; q < 8; q++) vv[q] = __ldg(&M[(size_t)ss[q] * 32 + lane]);
            __half2 p = __hadd2(
                __hadd2(__hadd2(u2h(vv[0]), u2h(vv[1])), __hadd2(u2h(vv[2]), u2h(vv[3]))),
                __hadd2(__hadd2(u2h(vv[4]), u2h(vv[5])), __hadd2(u2h(vv[6]), u2h(vv[7]))));
            float2 f = __half22float2(p);
            acc.x += f.x; acc.y += f.y;
        }
        if (j + 4 <= n) {
            int ss[4]; uint32_t vv[4];
            #pragma unroll
            for (int q = 0; q < 4; q++) ss[q] = __shfl_sync(0xffffffffu, myidx, j + q);
            #pragma unroll
            for (int q = 0; q < 4; q++) vv[q] = __ldg(&M[(size_t)ss[q] * 32 + lane]);
            __half2 p = __hadd2(__hadd2(u2h(vv[0]), u2h(vv[1])),
                                __hadd2(u2h(vv[2]), u2h(vv[3])));
            float2 f = __half22float2(p);
            acc.x += f.x; acc.y += f.y;
            j += 4;
        }
        for (; j < n; j++) {
            int s0 = __shfl_sync(0xffffffffu, myidx, j);
            float2 f = __half22float2(u2h(__ldg(&M[(size_t)s0 * 32 + lane])));
            acc.x += f.x; acc.y += f.y;
        }
    }
    float sc = __ldg(&isq[w]);
    float2 bb = __ldg(&((const float2*)b)[lane]);
    float gx = gelu_tanh(sc * acc.x + bb.x);
    float gy = gelu_tanh(sc * acc.y + bb.y);
    int g = __ldg(&batch[w]);
    float* p = sums + (size_t)g * 64 + (size_t)lane * 2;
    asm volatile("red.global.add.v2.f32 [%0], {%1,%2};" :: "l"(p), "f"(gx), "f"(gy) : "memory");
}

// ---------------- pool finalize (counts via binary search, per-thread) ----------------
__global__ void k_pool_fin(const float* __restrict__ sums, const int* __restrict__ batch,
                           float* __restrict__ out) {
    int i = blockIdx.x * blockDim.x + threadIdx.x;
    if (i >= NG * 64) return;
    int g = i >> 6;
    int lo = 0, hi = NN;
    while (lo < hi) { int mid = (lo + hi) >> 1; if (__ldg(&batch[mid]) < g) lo = mid + 1; else hi = mid; }
    int a = lo;
    lo = 0; hi = NN;
    while (lo < hi) { int mid = (lo + hi) >> 1; if (__ldg(&batch[mid]) < g + 1) lo = mid + 1; else hi = mid; }
    float c = fmaxf((float)(lo - a), 1.0f);
    out[i] = sums[i] / c;
}

// ---------------- launch ----------------
extern "C" void kernel_launch(void* const* d_in, const int* in_sizes, int n_in,
                              void* d_out, int out_size) {
    const float* x = (const float*)d_in[0];
    const int* ei = (const int*)d_in[1];
    const int* batch = (const int*)d_in[2];
    const float* W0 = (const float*)d_in[3];
    const float* b0 = (const float*)d_in[4];
    const float* W1 = (const float*)d_in[5];
    const float* b1 = (const float*)d_in[6];
    const float* W2 = (const float*)d_in[7];
    const float* b2 = (const float*)d_in[8];
    const int* src = ei;
    const int* dst = ei + NE;

    __half *xh, *msg, *hbuf;
    float *isq, *sums;
    int *cnti, *fill, *rowptr, *part, *offs, *csr, *sync;
    cudaGetSymbolAddress((void**)&xh, g_xh);
    cudaGetSymbolAddress((void**)&msg, g_msg);
    cudaGetSymbolAddress((void**)&hbuf, g_h);
    cudaGetSymbolAddress((void**)&isq, g_isq);
    cudaGetSymbolAddress((void**)&cnti, g_cnti);
    cudaGetSymbolAddress((void**)&fill, g_fill);
    cudaGetSymbolAddress((void**)&rowptr, g_rowptr);
    cudaGetSymbolAddress((void**)&part, g_part);
    cudaGetSymbolAddress((void**)&offs, g_offs);
    cudaGetSymbolAddress((void**)&csr, g_csr);
    cudaGetSymbolAddress((void**)&sums, g_sums);
    cudaGetSymbolAddress((void**)&sync, g_sync);

    const int SM128 = (128 * 136 + 2 * 128 * 136) * 2;  // 104448
    const int SM64  = (128 * 72 + 2 * 128 * 136) * 2;   // 88064
    cudaFuncSetAttribute(k_gemm_p<128>, cudaFuncAttributeMaxDynamicSharedMemorySize, SM128);
    cudaFuncSetAttribute(k_gemm_p<64>, cudaFuncAttributeMaxDynamicSharedMemorySize, SM64);

    // memsets (not kernel launches)
    cudaMemsetAsync(cnti, 0, NN * sizeof(int));
    cudaMemsetAsync(fill, 0, NN * sizeof(int));
    cudaMemsetAsync(sums, 0, NG * 64 * sizeof(float));
    cudaMemsetAsync(sync, 0, 4 * sizeof(int));

    // kernel launches — single stream; k_edgenode128 at index 3 for ncu capture
    k_prep<<<(NN * 32 + 255) / 256, 256>>>(x, xh, dst, cnti);                    // 0
    k_scanfill<<<SCAN_NB, 1024>>>(cnti, part, offs, isq, rowptr, sync,
                                  src, dst, fill, csr);                          // 1
    k_gemm_p<128><<<GEMM_GRID, 256, SM128>>>(xh, W0, isq, msg, NN);              // 2
    k_edgenode128<<<(NN * 32 + 255) / 256, 256>>>(rowptr, csr, isq, msg, b0, hbuf); // 3 <- profiled
    k_gemm_p<128><<<GEMM_GRID, 256, SM128>>>(hbuf, W1, isq, msg, NN);            // 4
    k_edgenode128<<<(NN * 32 + 255) / 256, 256>>>(rowptr, csr, isq, msg, b1, hbuf); // 5
    k_gemm_p<64><<<GEMM_GRID, 256, SM64>>>(hbuf, W2, isq, msg, NN);              // 6
    k_edgepool<<<(NN * 32 + 255) / 256, 256>>>(rowptr, csr, isq, msg, b2, batch, sums); // 7
    k_pool_fin<<<(NG * 64 + 255) / 256, 256>>>(sums, batch, (float*)d_out);      // 8
}

// round 15
// speedup vs baseline: 1.3095x; 1.0235x over previous
#include <cuda_runtime.h>
#include <cuda_fp16.h>
#include <cstdint>

#define NN 100000
#define NE 1600000
#define NG 256
#define SCAN_NB 98   // ceil(100000/1024)
#define NTILES 782   // ceil(100000/128)
#define GEMM_GRID 296

// ---------------- device scratch ----------------
__device__ __half g_xh[(size_t)NN * 128];    // x converted to fp16
__device__ __half g_msg[(size_t)NN * 128];   // xls = isq * (x@W), fp16
__device__ __half g_h[(size_t)NN * 128];     // h (fp16, GEMM input)
__device__ float  g_isq[NN];
__device__ int    g_cnti[NN];
__device__ int    g_fill[NN];
__device__ int    g_rowptr[NN + 1];
__device__ int    g_part[SCAN_NB + 2];
__device__ int    g_offs[SCAN_NB + 2];
__device__ int    g_csr[NE];                 // stores src<<5 (premultiplied row base)
__device__ float  g_sums[NG * 64];
__device__ int    g_sync[4];

// ---------------- helpers ----------------
__device__ __forceinline__ float gelu_tanh(float x) {
    const float c = 0.7978845608028654f;
    float x3 = x * x * x;
    return 0.5f * x * (1.0f + tanhf(c * (x + 0.044715f * x3)));
}

__device__ __forceinline__ __half2 u2h(uint32_t v) { return *reinterpret_cast<__half2*>(&v); }

__device__ __forceinline__ void acc_h2x2(float4& acc, uint2 v) {
    float2 lo = __half22float2(u2h(v.x));
    float2 hi = __half22float2(u2h(v.y));
    acc.x += lo.x; acc.y += lo.y; acc.z += hi.x; acc.w += hi.y;
}

__device__ __forceinline__ void ldsm_x4(uint32_t* r, uint32_t addr) {
    asm volatile("ldmatrix.sync.aligned.m8n8.x4.shared.b16 {%0,%1,%2,%3}, [%4];"
                 : "=r"(r[0]), "=r"(r[1]), "=r"(r[2]), "=r"(r[3]) : "r"(addr));
}
__device__ __forceinline__ void ldsm_x4_t(uint32_t* r, uint32_t addr) {
    asm volatile("ldmatrix.sync.aligned.m8n8.x4.trans.shared.b16 {%0,%1,%2,%3}, [%4];"
                 : "=r"(r[0]), "=r"(r[1]), "=r"(r[2]), "=r"(r[3]) : "r"(addr));
}
__device__ __forceinline__ void mma_f16(float4& d, const uint32_t a[4], uint32_t b0, uint32_t b1) {
    asm volatile(
        "mma.sync.aligned.m16n8k16.row.col.f32.f16.f16.f32 "
        "{%0,%1,%2,%3},{%4,%5,%6,%7},{%8,%9},{%0,%1,%2,%3};"
        : "+f"(d.x), "+f"(d.y), "+f"(d.z), "+f"(d.w)
        : "r"(a[0]), "r"(a[1]), "r"(a[2]), "r"(a[3]), "r"(b0), "r"(b1));
}
__device__ __forceinline__ void cp_commit() { asm volatile("cp.async.commit_group;"); }
template <int N>
__device__ __forceinline__ void cp_wait() { asm volatile("cp.async.wait_group %0;" :: "n"(N)); }

// ---------------- fused x->fp16 convert + degree count ----------------
__global__ void k_prep(const float* __restrict__ x, __half* __restrict__ xh,
                       const int* __restrict__ dst, int* __restrict__ cnt) {
    int i = blockIdx.x * blockDim.x + threadIdx.x;
    if (i < NN * 32) {
        float4 v = __ldg(&((const float4*)x)[i]);
        __half2 h0 = __floats2half2_rn(v.x, v.y);
        __half2 h1 = __floats2half2_rn(v.z, v.w);
        uint2 o; o.x = *(uint32_t*)&h0; o.y = *(uint32_t*)&h1;
        ((uint2*)xh)[i] = o;
    }
    if (i < NE) atomicAdd(&cnt[dst[i]], 1);
}

// ---------------- single-pass scan (shfl) + isq + rowptr + CSR fill ----------------
__global__ __launch_bounds__(1024) void k_scanfill(
    const int* __restrict__ cnt, int* __restrict__ part, int* __restrict__ offs,
    float* __restrict__ isq, int* __restrict__ rowptr, int* __restrict__ sync,
    const int* __restrict__ src, const int* __restrict__ dst,
    int* __restrict__ fill, int* __restrict__ csr) {
    __shared__ int wsum[32];
    __shared__ int is_last;
    int bid = blockIdx.x, t = threadIdx.x;
    int lane = t & 31, wid = t >> 5;
    int i = bid * 1024 + t;
    int v = (i < NN) ? cnt[i] : 0;
    if (i < NN) isq[i] = rsqrtf((float)v + 1.0f);

    // warp inclusive scan
    int xscan = v;
    #pragma unroll
    for (int d = 1; d < 32; d <<= 1) {
        int y = __shfl_up_sync(0xffffffffu, xscan, d);
        if (lane >= d) xscan += y;
    }
    if (lane == 31) wsum[wid] = xscan;
    __syncthreads();
    if (wid == 0) {
        int y = wsum[lane];
        #pragma unroll
        for (int d = 1; d < 32; d <<= 1) {
            int z = __shfl_up_sync(0xffffffffu, y, d);
            if (lane >= d) y += z;
        }
        wsum[lane] = y;
    }
    __syncthreads();
    int incl = xscan + (wid > 0 ? wsum[wid - 1] : 0);
    if (t == 1023) part[bid] = incl;
    __syncthreads();

    if (t == 0) {
        __threadfence();
        int old = atomicAdd(&sync[0], 1);
        is_last = (old == SCAN_NB - 1) ? 1 : 0;
    }
    __syncthreads();
    if (is_last) {
        // scan the 98 partials with a 128-wide Hillis-Steele (cheap, done once)
        __shared__ int sp[128];
        if (t < 128) sp[t] = (t < SCAN_NB) ? part[t] : 0;
        __syncthreads();
        for (int off = 1; off < 128; off <<= 1) {
            int tv = (t >= off && t < 128) ? sp[t - off] : 0;
            __syncthreads();
            if (t < 128) sp[t] += tv;
            __syncthreads();
        }
        if (t < SCAN_NB) offs[t] = (t == 0) ? 0 : sp[t - 1];
        __threadfence();
        __syncthreads();
        if (t == 0) atomicExch(&sync[1], 1);
    }
    if (t == 0) {
        while (*(volatile int*)&sync[1] == 0) { }
    }
    __syncthreads();
    __threadfence();
    int myoff = offs[bid];
    if (i < NN) rowptr[i + 1] = incl + myoff;
    if (i == 0) rowptr[0] = 0;

    if (t == 0) {
        __threadfence();
        atomicAdd(&sync[2], 1);
        while (*(volatile int*)&sync[2] < SCAN_NB) { }
    }
    __syncthreads();
    __threadfence();

    // CSR fill (premultiplied: store src<<5)
    for (int e = bid * 1024 + t; e < NE; e += SCAN_NB * 1024) {
        int d = __ldg(&dst[e]);
        int pos = rowptr[d] + atomicAdd(&fill[d], 1);
        csr[pos] = __ldg(&src[e]) << 5;
    }
}

// ---------------- pipelined fp16 tensor-core GEMM ----------------
template <int COUT>
__global__ __launch_bounds__(256, 2) void k_gemm_p(
    const __half* __restrict__ X, const float* __restrict__ W,
    const float* __restrict__ s, __half* __restrict__ Y, int n) {
    constexpr int WS = COUT + 8;
    constexpr int NT = COUT / 8;
    constexpr int STAGE = 128 * 136;
    constexpr int CPR = COUT / 8;
    extern __shared__ __half smh[];
    __half* sW = smh;             // [128][WS]
    __half* sX0 = smh + 128 * WS; // 2 x [128][136]
    int tid = threadIdx.x, lane = tid & 31, warp = tid >> 5;

    uint32_t sx_base = (uint32_t)__cvta_generic_to_shared(sX0);
    uint32_t sw_base = (uint32_t)__cvta_generic_to_shared(sW);

    auto load_tile = [&](int tile, int stage) {
        int row0 = tile * 128;
        uint32_t sb = sx_base + (uint32_t)(stage * STAGE * 2);
        #pragma unroll
        for (int i = tid; i < 128 * 16; i += 256) {
            int r = i >> 4, c = i & 15;
            int gr = row0 + r;
            if (gr < n)
                asm volatile("cp.async.cg.shared.global [%0], [%1], 16;"
                             :: "r"(sb + (uint32_t)(r * 272 + c * 16)),
                                "l"(X + (size_t)gr * 128 + c * 8));
        }
        cp_commit();
    };

    const int G = gridDim.x;
    int t0 = blockIdx.x;
    if (t0 < NTILES) load_tile(t0, 0);

    for (int i = tid; i < 128 * (COUT / 4); i += 256) {
        int k = i / (COUT / 4), c4 = (i % (COUT / 4)) * 4;
        float4 wv = __ldg(&((const float4*)W)[i]);
        __half2 h0 = __floats2half2_rn(wv.x, wv.y);
        __half2 h1 = __floats2half2_rn(wv.z, wv.w);
        uint2 o; o.x = *(uint32_t*)&h0; o.y = *(uint32_t*)&h1;
        *(uint2*)&sW[k * WS + c4] = o;
    }

    int stage = 0;
    int lane15 = lane & 15, laneh = (lane >> 4) << 3;
    int rw = warp * 16;

    for (int t = t0; t < NTILES; t += G) {
        int tn = t + G;
        if (tn < NTILES) { load_tile(tn, stage ^ 1); cp_wait<1>(); }
        else             { cp_wait<0>(); }
        __syncthreads();

        float4 acc[NT];
        #pragma unroll
        for (int q = 0; q < NT; q++) acc[q] = make_float4(0.f, 0.f, 0.f, 0.f);

        uint32_t sxs = sx_base + (uint32_t)(stage * STAGE * 2);
        __half* sXp = sX0 + stage * STAGE;
        #pragma unroll
        for (int kt = 0; kt < 8; kt++) {
            uint32_t afr[4];
            ldsm_x4(afr, sxs + (uint32_t)(((rw + lane15) * 136 + kt * 16 + laneh) * 2));
            #pragma unroll
            for (int np = 0; np < NT / 2; np++) {
                uint32_t bfr[4];
                ldsm_x4_t(bfr, sw_base + (uint32_t)(((kt * 16 + lane15) * WS + np * 16 + laneh) * 2));
                mma_f16(acc[2 * np], afr, bfr[0], bfr[1]);
                mma_f16(acc[2 * np + 1], afr, bfr[2], bfr[3]);
            }
        }

        int qid = lane >> 2, tq = lane & 3;
        int row0 = t * 128;
        int r1 = row0 + rw + qid, r2 = r1 + 8;
        float s1v = (r1 < n) ? __ldg(&s[r1]) : 0.f;
        float s2v = (r2 < n) ? __ldg(&s[r2]) : 0.f;
        #pragma unroll
        for (int nt = 0; nt < NT; nt++) {
            int c = nt * 8 + 2 * tq;
            *(__half2*)&sXp[(rw + qid) * 136 + c]     = __floats2half2_rn(s1v * acc[nt].x, s1v * acc[nt].y);
            *(__half2*)&sXp[(rw + qid + 8) * 136 + c] = __floats2half2_rn(s2v * acc[nt].z, s2v * acc[nt].w);
        }
        __syncwarp();
        #pragma unroll
        for (int q = 0; q < 16 * CPR / 32; q++) {
            int idx = q * 32 + lane;
            int r = idx / CPR, c = idx % CPR;
            int gr = row0 + rw + r;
            if (gr < n)
                *(uint4*)&Y[(size_t)gr * COUT + c * 8] = *(uint4*)&sXp[(rw + r) * 136 + c * 8];
        }
        __syncthreads();
        stage ^= 1;
    }
}

// ---------------- fused edge gather + node epilogue (premultiplied csr, depth-2 tree) ----------------
// h[i] = gelu( isq[i] * (sum_{j in N(i)} msg[j] + msg[i]) + b )   (h fp16)
__global__ __launch_bounds__(256) void k_edgenode128(
    const int* __restrict__ rp, const int* __restrict__ csr,
    const float* __restrict__ isq, const __half* __restrict__ msg,
    const float* __restrict__ b, __half* __restrict__ h) {
    int w = (blockIdx.x * blockDim.x + threadIdx.x) >> 5;
    int lane = threadIdx.x & 31;
    if (w >= NN) return;
    int e0 = __ldg(&rp[w]), e1 = __ldg(&rp[w + 1]);
    const uint2* M = (const uint2*)msg;
    float4 acc = make_float4(0.f, 0.f, 0.f, 0.f);
    acc_h2x2(acc, __ldg(&M[(unsigned)(w * 32 + lane)]));   // self

    for (int base = e0; base < e1; base += 32) {
        int n = e1 - base; if (n > 32) n = 32;
        int myidx = 0;
        if (lane < n) myidx = __ldg(&csr[base + lane]);   // premultiplied (src<<5)
        int j = 0;
        for (; j + 8 <= n; j += 8) {
            int ss[8]; uint2 vv[8];
            #pragma unroll
            for (int q = 0; q < 8; q++) ss[q] = __shfl_sync(0xffffffffu, myidx, j + q);
            #pragma unroll
            for (int q = 0; q < 8; q++) vv[q] = __ldg(&M[(unsigned)(ss[q] + lane)]);
            // two depth-2 fp16 trees, fp32 final accumulate
            #pragma unroll
            for (int g = 0; g < 2; g++) {
                __half2 px = __hadd2(__hadd2(u2h(vv[4*g].x), u2h(vv[4*g+1].x)),
                                     __hadd2(u2h(vv[4*g+2].x), u2h(vv[4*g+3].x)));
                __half2 py = __hadd2(__hadd2(u2h(vv[4*g].y), u2h(vv[4*g+1].y)),
                                     __hadd2(u2h(vv[4*g+2].y), u2h(vv[4*g+3].y)));
                float2 fx = __half22float2(px);
                float2 fy = __half22float2(py);
                acc.x += fx.x; acc.y += fx.y; acc.z += fy.x; acc.w += fy.y;
            }
        }
        if (j + 4 <= n) {
            int ss[4]; uint2 vv[4];
            #pragma unroll
            for (int q = 0; q < 4; q++) ss[q] = __shfl_sync(0xffffffffu, myidx, j + q);
            #pragma unroll
            for (int q = 0; q < 4; q++) vv[q] = __ldg(&M[(unsigned)(ss[q] + lane)]);
            __half2 px = __hadd2(__hadd2(u2h(vv[0].x), u2h(vv[1].x)),
                                 __hadd2(u2h(vv[2].x), u2h(vv[3].x)));
            __half2 py = __hadd2(__hadd2(u2h(vv[0].y), u2h(vv[1].y)),
                                 __hadd2(u2h(vv[2].y), u2h(vv[3].y)));
            float2 fx = __half22float2(px);
            float2 fy = __half22float2(py);
            acc.x += fx.x; acc.y += fx.y; acc.z += fy.x; acc.w += fy.y;
            j += 4;
        }
        for (; j < n; j++) {
            int s0 = __shfl_sync(0xffffffffu, myidx, j);
            acc_h2x2(acc, __ldg(&M[(unsigned)(s0 + lane)]));
        }
    }
    float sc = __ldg(&isq[w]);
    float4 bb = __ldg(&((const float4*)b)[lane]);
    __half2 p0 = __floats2half2_rn(gelu_tanh(sc * acc.x + bb.x), gelu_tanh(sc * acc.y + bb.y));
    __half2 p1 = __floats2half2_rn(gelu_tanh(sc * acc.z + bb.z), gelu_tanh(sc * acc.w + bb.w));
    uint2 out; out.x = *(uint32_t*)&p0; out.y = *(uint32_t*)&p1;
    ((uint2*)h)[(size_t)w * 32 + lane] = out;
}

// final layer: gather (COUT=64) + gelu + fused mean-pool reduction into sums
__global__ __launch_bounds__(256) void k_edgepool(
    const int* __restrict__ rp, const int* __restrict__ csr,
    const float* __restrict__ isq, const __half* __restrict__ msg,
    const float* __restrict__ b, const int* __restrict__ batch,
    float* __restrict__ sums) {
    int w = (blockIdx.x * blockDim.x + threadIdx.x) >> 5;
    int lane = threadIdx.x & 31;
    if (w >= NN) return;
    int e0 = __ldg(&rp[w]), e1 = __ldg(&rp[w + 1]);
    const uint32_t* M = (const uint32_t*)msg;   // 32 uint32 per row (COUT=64)
    float2 acc = __half22float2(u2h(__ldg(&M[(unsigned)(w * 32 + lane)])));

    for (int base = e0; base < e1; base += 32) {
        int n = e1 - base; if (n > 32) n = 32;
        int myidx = 0;
        if (lane < n) myidx = __ldg(&csr[base + lane]);   // premultiplied
        int j = 0;
        for (; j + 8 <= n; j += 8) {
            int ss[8]; uint32_t vv[8];
            #pragma unroll
            for (int q = 0; q < 8; q++) ss[q] = __shfl_sync(0xffffffffu, myidx, j + q);
            #pragma unroll
            for (int q = 0; q < 8; q++) vv[q] = __ldg(&M[(unsigned)(ss[q] + lane)]);
            #pragma unroll
            for (int g = 0; g < 2; g++) {
                __half2 p = __hadd2(__hadd2(u2h(vv[4*g]), u2h(vv[4*g+1])),
                                    __hadd2(u2h(vv[4*g+2]), u2h(vv[4*g+3])));
                float2 f = __half22float2(p);
                acc.x += f.x; acc.y += f.y;
            }
        }
        if (j + 4 <= n) {
            int ss[4]; uint32_t vv[4];
            #pragma unroll
            for (int q = 0; q < 4; q++) ss[q] = __shfl_sync(0xffffffffu, myidx, j + q);
            #pragma unroll
            for (int q = 0; q < 4; q++) vv[q] = __ldg(&M[(unsigned)(ss[q] + lane)]);
            __half2 p = __hadd2(__hadd2(u2h(vv[0]), u2h(vv[1])),
                                __hadd2(u2h(vv[2]), u2h(vv[3])));
            float2 f = __half22float2(p);
            acc.x += f.x; acc.y += f.y;
            j += 4;
        }
        for (; j < n; j++) {
            int s0 = __shfl_sync(0xffffffffu, myidx, j);
            float2 f = __half22float2(u2h(__ldg(&M[(unsigned)(s0 + lane)])));
            acc.x += f.x; acc.y += f.y;
        }
    }
    float sc = __ldg(&isq[w]);
    float2 bb = __ldg(&((const float2*)b)[lane]);
    float gx = gelu_tanh(sc * acc.x + bb.x);
    float gy = gelu_tanh(sc * acc.y + bb.y);
    int g = __ldg(&batch[w]);
    float* p = sums + (size_t)g * 64 + (size_t)lane * 2;
    asm volatile("red.global.add.v2.f32 [%0], {%1,%2};" :: "l"(p), "f"(gx), "f"(gy) : "memory");
}

// ---------------- pool finalize (counts via binary search, per-thread) ----------------
__global__ void k_pool_fin(const float* __restrict__ sums, const int* __restrict__ batch,
                           float* __restrict__ out) {
    int i = blockIdx.x * blockDim.x + threadIdx.x;
    if (i >= NG * 64) return;
    int g = i >> 6;
    int lo = 0, hi = NN;
    while (lo < hi) { int mid = (lo + hi) >> 1; if (__ldg(&batch[mid]) < g) lo = mid + 1; else hi = mid; }
    int a = lo;
    lo = 0; hi = NN;
    while (lo < hi) { int mid = (lo + hi) >> 1; if (__ldg(&batch[mid]) < g + 1) lo = mid + 1; else hi = mid; }
    float c = fmaxf((float)(lo - a), 1.0f);
    out[i] = sums[i] / c;
}

// ---------------- launch ----------------
extern "C" void kernel_launch(void* const* d_in, const int* in_sizes, int n_in,
                              void* d_out, int out_size) {
    const float* x = (const float*)d_in[0];
    const int* ei = (const int*)d_in[1];
    const int* batch = (const int*)d_in[2];
    const float* W0 = (const float*)d_in[3];
    const float* b0 = (const float*)d_in[4];
    const float* W1 = (const float*)d_in[5];
    const float* b1 = (const float*)d_in[6];
    const float* W2 = (const float*)d_in[7];
    const float* b2 = (const float*)d_in[8];
    const int* src = ei;
    const int* dst = ei + NE;

    __half *xh, *msg, *hbuf;
    float *isq, *sums;
    int *cnti, *fill, *rowptr, *part, *offs, *csr, *sync;
    cudaGetSymbolAddress((void**)&xh, g_xh);
    cudaGetSymbolAddress((void**)&msg, g_msg);
    cudaGetSymbolAddress((void**)&hbuf, g_h);
    cudaGetSymbolAddress((void**)&isq, g_isq);
    cudaGetSymbolAddress((void**)&cnti, g_cnti);
    cudaGetSymbolAddress((void**)&fill, g_fill);
    cudaGetSymbolAddress((void**)&rowptr, g_rowptr);
    cudaGetSymbolAddress((void**)&part, g_part);
    cudaGetSymbolAddress((void**)&offs, g_offs);
    cudaGetSymbolAddress((void**)&csr, g_csr);
    cudaGetSymbolAddress((void**)&sums, g_sums);
    cudaGetSymbolAddress((void**)&sync, g_sync);

    const int SM128 = (128 * 136 + 2 * 128 * 136) * 2;  // 104448
    const int SM64  = (128 * 72 + 2 * 128 * 136) * 2;   // 88064
    cudaFuncSetAttribute(k_gemm_p<128>, cudaFuncAttributeMaxDynamicSharedMemorySize, SM128);
    cudaFuncSetAttribute(k_gemm_p<64>, cudaFuncAttributeMaxDynamicSharedMemorySize, SM64);

    // memsets (not kernel launches)
    cudaMemsetAsync(cnti, 0, NN * sizeof(int));
    cudaMemsetAsync(fill, 0, NN * sizeof(int));
    cudaMemsetAsync(sums, 0, NG * 64 * sizeof(float));
    cudaMemsetAsync(sync, 0, 4 * sizeof(int));

    // kernel launches — single stream; k_edgenode128 at index 3 for ncu capture
    k_prep<<<(NN * 32 + 255) / 256, 256>>>(x, xh, dst, cnti);                    // 0
    k_scanfill<<<SCAN_NB, 1024>>>(cnti, part, offs, isq, rowptr, sync,
                                  src, dst, fill, csr);                          // 1
    k_gemm_p<128><<<GEMM_GRID, 256, SM128>>>(xh, W0, isq, msg, NN);              // 2
    k_edgenode128<<<(NN * 32 + 255) / 256, 256>>>(rowptr, csr, isq, msg, b0, hbuf); // 3 <- profiled
    k_gemm_p<128><<<GEMM_GRID, 256, SM128>>>(hbuf, W1, isq, msg, NN);            // 4
    k_edgenode128<<<(NN * 32 + 255) / 256, 256>>>(rowptr, csr, isq, msg, b1, hbuf); // 5
    k_gemm_p<64><<<GEMM_GRID, 256, SM64>>>(hbuf, W2, isq, msg, NN);              // 6
    k_edgepool<<<(NN * 32 + 255) / 256, 256>>>(rowptr, csr, isq, msg, b2, batch, sums); // 7
    k_pool_fin<<<(NG * 64 + 255) / 256, 256>>>(sums, batch, (float*)d_out);      // 8
}

// round 16
// speedup vs baseline: 1.3637x; 1.0414x over previous
#include <cuda_runtime.h>
#include <cuda_fp16.h>
#include <cstdint>

#define NN 100000
#define NE 1600000
#define NG 256
#define SCAN_NB 98   // ceil(100000/1024)
#define NTILES 782   // ceil(100000/128)
#define GEMM_GRID 296

// ---------------- device scratch ----------------
__device__ __half g_xh[(size_t)NN * 128];    // x converted to fp16
__device__ __half g_msg[(size_t)NN * 128];   // xls = isq * (x@W), fp16
__device__ __half g_h[(size_t)NN * 128];     // h (fp16, GEMM input)
__device__ float  g_isq[NN];
__device__ int    g_cnti[NN];
__device__ int    g_fill[NN];
__device__ int    g_rowptr[NN + 1];
__device__ int    g_part[SCAN_NB + 2];
__device__ int    g_offs[SCAN_NB + 2];
__device__ int    g_csr[NE];                 // stores src<<5 (premultiplied row base)
__device__ float  g_sums[NG * 64];
__device__ int    g_sync[4];

// ---------------- helpers ----------------
__device__ __forceinline__ float tanh_hw(float x) {
    float y;
    asm("tanh.approx.f32 %0, %1;" : "=f"(y) : "f"(x));
    return y;
}
__device__ __forceinline__ float gelu_tanh(float x) {
    const float c = 0.7978845608028654f;
    float x3 = x * x * x;
    return 0.5f * x * (1.0f + tanh_hw(c * (x + 0.044715f * x3)));
}

__device__ __forceinline__ __half2 u2h(uint32_t v) { return *reinterpret_cast<__half2*>(&v); }

__device__ __forceinline__ void acc_h2x2(float4& acc, uint2 v) {
    float2 lo = __half22float2(u2h(v.x));
    float2 hi = __half22float2(u2h(v.y));
    acc.x += lo.x; acc.y += lo.y; acc.z += hi.x; acc.w += hi.y;
}

__device__ __forceinline__ void ldsm_x4(uint32_t* r, uint32_t addr) {
    asm volatile("ldmatrix.sync.aligned.m8n8.x4.shared.b16 {%0,%1,%2,%3}, [%4];"
                 : "=r"(r[0]), "=r"(r[1]), "=r"(r[2]), "=r"(r[3]) : "r"(addr));
}
__device__ __forceinline__ void ldsm_x4_t(uint32_t* r, uint32_t addr) {
    asm volatile("ldmatrix.sync.aligned.m8n8.x4.trans.shared.b16 {%0,%1,%2,%3}, [%4];"
                 : "=r"(r[0]), "=r"(r[1]), "=r"(r[2]), "=r"(r[3]) : "r"(addr));
}
__device__ __forceinline__ void mma_f16(float4& d, const uint32_t a[4], uint32_t b0, uint32_t b1) {
    asm volatile(
        "mma.sync.aligned.m16n8k16.row.col.f32.f16.f16.f32 "
        "{%0,%1,%2,%3},{%4,%5,%6,%7},{%8,%9},{%0,%1,%2,%3};"
        : "+f"(d.x), "+f"(d.y), "+f"(d.z), "+f"(d.w)
        : "r"(a[0]), "r"(a[1]), "r"(a[2]), "r"(a[3]), "r"(b0), "r"(b1));
}
__device__ __forceinline__ void cp_commit() { asm volatile("cp.async.commit_group;"); }
template <int N>
__device__ __forceinline__ void cp_wait() { asm volatile("cp.async.wait_group %0;" :: "n"(N)); }

// ---------------- fused x->fp16 convert + degree count ----------------
__global__ void k_prep(const float* __restrict__ x, __half* __restrict__ xh,
                       const int* __restrict__ dst, int* __restrict__ cnt) {
    int i = blockIdx.x * blockDim.x + threadIdx.x;
    if (i < NN * 32) {
        float4 v = __ldg(&((const float4*)x)[i]);
        __half2 h0 = __floats2half2_rn(v.x, v.y);
        __half2 h1 = __floats2half2_rn(v.z, v.w);
        uint2 o; o.x = *(uint32_t*)&h0; o.y = *(uint32_t*)&h1;
        ((uint2*)xh)[i] = o;
    }
    if (i < NE) atomicAdd(&cnt[dst[i]], 1);
}

// ---------------- single-pass scan (shfl) + isq + rowptr + CSR fill ----------------
__global__ __launch_bounds__(1024) void k_scanfill(
    const int* __restrict__ cnt, int* __restrict__ part, int* __restrict__ offs,
    float* __restrict__ isq, int* __restrict__ rowptr, int* __restrict__ sync,
    const int* __restrict__ src, const int* __restrict__ dst,
    int* __restrict__ fill, int* __restrict__ csr) {
    __shared__ int wsum[32];
    __shared__ int is_last;
    int bid = blockIdx.x, t = threadIdx.x;
    int lane = t & 31, wid = t >> 5;
    int i = bid * 1024 + t;
    int v = (i < NN) ? cnt[i] : 0;
    if (i < NN) isq[i] = rsqrtf((float)v + 1.0f);

    int xscan = v;
    #pragma unroll
    for (int d = 1; d < 32; d <<= 1) {
        int y = __shfl_up_sync(0xffffffffu, xscan, d);
        if (lane >= d) xscan += y;
    }
    if (lane == 31) wsum[wid] = xscan;
    __syncthreads();
    if (wid == 0) {
        int y = wsum[lane];
        #pragma unroll
        for (int d = 1; d < 32; d <<= 1) {
            int z = __shfl_up_sync(0xffffffffu, y, d);
            if (lane >= d) y += z;
        }
        wsum[lane] = y;
    }
    __syncthreads();
    int incl = xscan + (wid > 0 ? wsum[wid - 1] : 0);
    if (t == 1023) part[bid] = incl;
    __syncthreads();

    if (t == 0) {
        __threadfence();
        int old = atomicAdd(&sync[0], 1);
        is_last = (old == SCAN_NB - 1) ? 1 : 0;
    }
    __syncthreads();
    if (is_last) {
        __shared__ int sp[128];
        if (t < 128) sp[t] = (t < SCAN_NB) ? part[t] : 0;
        __syncthreads();
        for (int off = 1; off < 128; off <<= 1) {
            int tv = (t >= off && t < 128) ? sp[t - off] : 0;
            __syncthreads();
            if (t < 128) sp[t] += tv;
            __syncthreads();
        }
        if (t < SCAN_NB) offs[t] = (t == 0) ? 0 : sp[t - 1];
        __threadfence();
        __syncthreads();
        if (t == 0) atomicExch(&sync[1], 1);
    }
    if (t == 0) {
        while (*(volatile int*)&sync[1] == 0) { }
    }
    __syncthreads();
    __threadfence();
    int myoff = offs[bid];
    if (i < NN) rowptr[i + 1] = incl + myoff;
    if (i == 0) rowptr[0] = 0;

    if (t == 0) {
        __threadfence();
        atomicAdd(&sync[2], 1);
        while (*(volatile int*)&sync[2] < SCAN_NB) { }
    }
    __syncthreads();
    __threadfence();

    for (int e = bid * 1024 + t; e < NE; e += SCAN_NB * 1024) {
        int d = __ldg(&dst[e]);
        int pos = rowptr[d] + atomicAdd(&fill[d], 1);
        csr[pos] = __ldg(&src[e]) << 5;
    }
}

// ---------------- pipelined fp16 tensor-core GEMM ----------------
template <int COUT>
__global__ __launch_bounds__(256, 2) void k_gemm_p(
    const __half* __restrict__ X, const float* __restrict__ W,
    const float* __restrict__ s, __half* __restrict__ Y, int n) {
    constexpr int WS = COUT + 8;
    constexpr int NT = COUT / 8;
    constexpr int STAGE = 128 * 136;
    constexpr int CPR = COUT / 8;
    extern __shared__ __half smh[];
    __half* sW = smh;             // [128][WS]
    __half* sX0 = smh + 128 * WS; // 2 x [128][136]
    int tid = threadIdx.x, lane = tid & 31, warp = tid >> 5;

    uint32_t sx_base = (uint32_t)__cvta_generic_to_shared(sX0);
    uint32_t sw_base = (uint32_t)__cvta_generic_to_shared(sW);

    auto load_tile = [&](int tile, int stage) {
        int row0 = tile * 128;
        uint32_t sb = sx_base + (uint32_t)(stage * STAGE * 2);
        #pragma unroll
        for (int i = tid; i < 128 * 16; i += 256) {
            int r = i >> 4, c = i & 15;
            int gr = row0 + r;
            if (gr < n)
                asm volatile("cp.async.cg.shared.global [%0], [%1], 16;"
                             :: "r"(sb + (uint32_t)(r * 272 + c * 16)),
                                "l"(X + (size_t)gr * 128 + c * 8));
        }
        cp_commit();
    };

    const int G = gridDim.x;
    int t0 = blockIdx.x;
    if (t0 < NTILES) load_tile(t0, 0);

    for (int i = tid; i < 128 * (COUT / 4); i += 256) {
        int k = i / (COUT / 4), c4 = (i % (COUT / 4)) * 4;
        float4 wv = __ldg(&((const float4*)W)[i]);
        __half2 h0 = __floats2half2_rn(wv.x, wv.y);
        __half2 h1 = __floats2half2_rn(wv.z, wv.w);
        uint2 o; o.x = *(uint32_t*)&h0; o.y = *(uint32_t*)&h1;
        *(uint2*)&sW[k * WS + c4] = o;
    }

    int stage = 0;
    int lane15 = lane & 15, laneh = (lane >> 4) << 3;
    int rw = warp * 16;

    for (int t = t0; t < NTILES; t += G) {
        int tn = t + G;
        if (tn < NTILES) { load_tile(tn, stage ^ 1); cp_wait<1>(); }
        else             { cp_wait<0>(); }
        __syncthreads();

        float4 acc[NT];
        #pragma unroll
        for (int q = 0; q < NT; q++) acc[q] = make_float4(0.f, 0.f, 0.f, 0.f);

        uint32_t sxs = sx_base + (uint32_t)(stage * STAGE * 2);
        __half* sXp = sX0 + stage * STAGE;
        #pragma unroll
        for (int kt = 0; kt < 8; kt++) {
            uint32_t afr[4];
            ldsm_x4(afr, sxs + (uint32_t)(((rw + lane15) * 136 + kt * 16 + laneh) * 2));
            #pragma unroll
            for (int np = 0; np < NT / 2; np++) {
                uint32_t bfr[4];
                ldsm_x4_t(bfr, sw_base + (uint32_t)(((kt * 16 + lane15) * WS + np * 16 + laneh) * 2));
                mma_f16(acc[2 * np], afr, bfr[0], bfr[1]);
                mma_f16(acc[2 * np + 1], afr, bfr[2], bfr[3]);
            }
        }

        int qid = lane >> 2, tq = lane & 3;
        int row0 = t * 128;
        int r1 = row0 + rw + qid, r2 = r1 + 8;
        float s1v = (r1 < n) ? __ldg(&s[r1]) : 0.f;
        float s2v = (r2 < n) ? __ldg(&s[r2]) : 0.f;
        #pragma unroll
        for (int nt = 0; nt < NT; nt++) {
            int c = nt * 8 + 2 * tq;
            *(__half2*)&sXp[(rw + qid) * 136 + c]     = __floats2half2_rn(s1v * acc[nt].x, s1v * acc[nt].y);
            *(__half2*)&sXp[(rw + qid + 8) * 136 + c] = __floats2half2_rn(s2v * acc[nt].z, s2v * acc[nt].w);
        }
        __syncwarp();
        #pragma unroll
        for (int q = 0; q < 16 * CPR / 32; q++) {
            int idx = q * 32 + lane;
            int r = idx / CPR, c = idx % CPR;
            int gr = row0 + rw + r;
            if (gr < n)
                *(uint4*)&Y[(size_t)gr * COUT + c * 8] = *(uint4*)&sXp[(rw + r) * 136 + c * 8];
        }
        __syncthreads();
        stage ^= 1;
    }
}

// ---------------- fused edge gather + node epilogue (premultiplied csr, depth-2 tree) ----------------
// h[i] = gelu( isq[i] * (sum_{j in N(i)} msg[j] + msg[i]) + b )   (h fp16)
__global__ __launch_bounds__(256) void k_edgenode128(
    const int* __restrict__ rp, const int* __restrict__ csr,
    const float* __restrict__ isq, const __half* __restrict__ msg,
    const float* __restrict__ b, __half* __restrict__ h) {
    int w = (blockIdx.x * blockDim.x + threadIdx.x) >> 5;
    int lane = threadIdx.x & 31;
    if (w >= NN) return;
    int e0 = __ldg(&rp[w]), e1 = __ldg(&rp[w + 1]);
    const uint2* M = (const uint2*)msg;
    float4 acc = make_float4(0.f, 0.f, 0.f, 0.f);
    acc_h2x2(acc, __ldg(&M[(unsigned)(w * 32 + lane)]));   // self

    for (int base = e0; base < e1; base += 32) {
        int n = e1 - base; if (n > 32) n = 32;
        int myidx = 0;
        if (lane < n) myidx = __ldg(&csr[base + lane]);   // premultiplied (src<<5)
        int j = 0;
        for (; j + 8 <= n; j += 8) {
            int ss[8]; uint2 vv[8];
            #pragma unroll
            for (int q = 0; q < 8; q++) ss[q] = __shfl_sync(0xffffffffu, myidx, j + q);
            #pragma unroll
            for (int q = 0; q < 8; q++) vv[q] = __ldg(&M[(unsigned)(ss[q] + lane)]);
            #pragma unroll
            for (int g = 0; g < 2; g++) {
                __half2 px = __hadd2(__hadd2(u2h(vv[4*g].x), u2h(vv[4*g+1].x)),
                                     __hadd2(u2h(vv[4*g+2].x), u2h(vv[4*g+3].x)));
                __half2 py = __hadd2(__hadd2(u2h(vv[4*g].y), u2h(vv[4*g+1].y)),
                                     __hadd2(u2h(vv[4*g+2].y), u2h(vv[4*g+3].y)));
                float2 fx = __half22float2(px);
                float2 fy = __half22float2(py);
                acc.x += fx.x; acc.y += fx.y; acc.z += fy.x; acc.w += fy.y;
            }
        }
        if (j + 4 <= n) {
            int ss[4]; uint2 vv[4];
            #pragma unroll
            for (int q = 0; q < 4; q++) ss[q] = __shfl_sync(0xffffffffu, myidx, j + q);
            #pragma unroll
            for (int q = 0; q < 4; q++) vv[q] = __ldg(&M[(unsigned)(ss[q] + lane)]);
            __half2 px = __hadd2(__hadd2(u2h(vv[0].x), u2h(vv[1].x)),
                                 __hadd2(u2h(vv[2].x), u2h(vv[3].x)));
            __half2 py = __hadd2(__hadd2(u2h(vv[0].y), u2h(vv[1].y)),
                                 __hadd2(u2h(vv[2].y), u2h(vv[3].y)));
            float2 fx = __half22float2(px);
            float2 fy = __half22float2(py);
            acc.x += fx.x; acc.y += fx.y; acc.z += fy.x; acc.w += fy.y;
            j += 4;
        }
        for (; j < n; j++) {
            int s0 = __shfl_sync(0xffffffffu, myidx, j);
            acc_h2x2(acc, __ldg(&M[(unsigned)(s0 + lane)]));
        }
    }
    float sc = __ldg(&isq[w]);
    float4 bb = __ldg(&((const float4*)b)[lane]);
    __half2 p0 = __floats2half2_rn(gelu_tanh(sc * acc.x + bb.x), gelu_tanh(sc * acc.y + bb.y));
    __half2 p1 = __floats2half2_rn(gelu_tanh(sc * acc.z + bb.z), gelu_tanh(sc * acc.w + bb.w));
    uint2 out; out.x = *(uint32_t*)&p0; out.y = *(uint32_t*)&p1;
    ((uint2*)h)[(size_t)w * 32 + lane] = out;
}

// final layer: gather (COUT=64) + gelu + fused mean-pool reduction into sums
__global__ __launch_bounds__(256) void k_edgepool(
    const int* __restrict__ rp, const int* __restrict__ csr,
    const float* __restrict__ isq, const __half* __restrict__ msg,
    const float* __restrict__ b, const int* __restrict__ batch,
    float* __restrict__ sums) {
    int w = (blockIdx.x * blockDim.x + threadIdx.x) >> 5;
    int lane = threadIdx.x & 31;
    if (w >= NN) return;
    int e0 = __ldg(&rp[w]), e1 = __ldg(&rp[w + 1]);
    const uint32_t* M = (const uint32_t*)msg;   // 32 uint32 per row (COUT=64)
    float2 acc = __half22float2(u2h(__ldg(&M[(unsigned)(w * 32 + lane)])));

    for (int base = e0; base < e1; base += 32) {
        int n = e1 - base; if (n > 32) n = 32;
        int myidx = 0;
        if (lane < n) myidx = __ldg(&csr[base + lane]);   // premultiplied
        int j = 0;
        for (; j + 8 <= n; j += 8) {
            int ss[8]; uint32_t vv[8];
            #pragma unroll
            for (int q = 0; q < 8; q++) ss[q] = __shfl_sync(0xffffffffu, myidx, j + q);
            #pragma unroll
            for (int q = 0; q < 8; q++) vv[q] = __ldg(&M[(unsigned)(ss[q] + lane)]);
            #pragma unroll
            for (int g = 0; g < 2; g++) {
                __half2 p = __hadd2(__hadd2(u2h(vv[4*g]), u2h(vv[4*g+1])),
                                    __hadd2(u2h(vv[4*g+2]), u2h(vv[4*g+3])));
                float2 f = __half22float2(p);
                acc.x += f.x; acc.y += f.y;
            }
        }
        if (j + 4 <= n) {
            int ss[4]; uint32_t vv[4];
            #pragma unroll
            for (int q = 0; q < 4; q++) ss[q] = __shfl_sync(0xffffffffu, myidx, j + q);
            #pragma unroll
            for (int q = 0; q < 4; q++) vv[q] = __ldg(&M[(unsigned)(ss[q] + lane)]);
            __half2 p = __hadd2(__hadd2(u2h(vv[0]), u2h(vv[1])),
                                __hadd2(u2h(vv[2]), u2h(vv[3])));
            float2 f = __half22float2(p);
            acc.x += f.x; acc.y += f.y;
            j += 4;
        }
        for (; j < n; j++) {
            int s0 = __shfl_sync(0xffffffffu, myidx, j);
            float2 f = __half22float2(u2h(__ldg(&M[(unsigned)(s0 + lane)])));
            acc.x += f.x; acc.y += f.y;
        }
    }
    float sc = __ldg(&isq[w]);
    float2 bb = __ldg(&((const float2*)b)[lane]);
    float gx = gelu_tanh(sc * acc.x + bb.x);
    float gy = gelu_tanh(sc * acc.y + bb.y);
    int g = __ldg(&batch[w]);
    float* p = sums + (size_t)g * 64 + (size_t)lane * 2;
    asm volatile("red.global.add.v2.f32 [%0], {%1,%2};" :: "l"(p), "f"(gx), "f"(gy) : "memory");
}

// ---------------- pool finalize (counts via binary search, per-thread) ----------------
__global__ void k_pool_fin(const float* __restrict__ sums, const int* __restrict__ batch,
                           float* __restrict__ out) {
    int i = blockIdx.x * blockDim.x + threadIdx.x;
    if (i >= NG * 64) return;
    int g = i >> 6;
    int lo = 0, hi = NN;
    while (lo < hi) { int mid = (lo + hi) >> 1; if (__ldg(&batch[mid]) < g) lo = mid + 1; else hi = mid; }
    int a = lo;
    lo = 0; hi = NN;
    while (lo < hi) { int mid = (lo + hi) >> 1; if (__ldg(&batch[mid]) < g + 1) lo = mid + 1; else hi = mid; }
    float c = fmaxf((float)(lo - a), 1.0f);
    out[i] = sums[i] / c;
}

// ---------------- launch ----------------
extern "C" void kernel_launch(void* const* d_in, const int* in_sizes, int n_in,
                              void* d_out, int out_size) {
    const float* x = (const float*)d_in[0];
    const int* ei = (const int*)d_in[1];
    const int* batch = (const int*)d_in[2];
    const float* W0 = (const float*)d_in[3];
    const float* b0 = (const float*)d_in[4];
    const float* W1 = (const float*)d_in[5];
    const float* b1 = (const float*)d_in[6];
    const float* W2 = (const float*)d_in[7];
    const float* b2 = (const float*)d_in[8];
    const int* src = ei;
    const int* dst = ei + NE;

    __half *xh, *msg, *hbuf;
    float *isq, *sums;
    int *cnti, *fill, *rowptr, *part, *offs, *csr, *sync;
    cudaGetSymbolAddress((void**)&xh, g_xh);
    cudaGetSymbolAddress((void**)&msg, g_msg);
    cudaGetSymbolAddress((void**)&hbuf, g_h);
    cudaGetSymbolAddress((void**)&isq, g_isq);
    cudaGetSymbolAddress((void**)&cnti, g_cnti);
    cudaGetSymbolAddress((void**)&fill, g_fill);
    cudaGetSymbolAddress((void**)&rowptr, g_rowptr);
    cudaGetSymbolAddress((void**)&part, g_part);
    cudaGetSymbolAddress((void**)&offs, g_offs);
    cudaGetSymbolAddress((void**)&csr, g_csr);
    cudaGetSymbolAddress((void**)&sums, g_sums);
    cudaGetSymbolAddress((void**)&sync, g_sync);

    const int SM128 = (128 * 136 + 2 * 128 * 136) * 2;  // 104448
    const int SM64  = (128 * 72 + 2 * 128 * 136) * 2;   // 88064
    cudaFuncSetAttribute(k_gemm_p<128>, cudaFuncAttributeMaxDynamicSharedMemorySize, SM128);
    cudaFuncSetAttribute(k_gemm_p<64>, cudaFuncAttributeMaxDynamicSharedMemorySize, SM64);

    // memsets (not kernel launches)
    cudaMemsetAsync(cnti, 0, NN * sizeof(int));
    cudaMemsetAsync(fill, 0, NN * sizeof(int));
    cudaMemsetAsync(sums, 0, NG * 64 * sizeof(float));
    cudaMemsetAsync(sync, 0, 4 * sizeof(int));

    // kernel launches — single stream; k_edgenode128 at index 3 for ncu capture
    k_prep<<<(NN * 32 + 255) / 256, 256>>>(x, xh, dst, cnti);                    // 0
    k_scanfill<<<SCAN_NB, 1024>>>(cnti, part, offs, isq, rowptr, sync,
                                  src, dst, fill, csr);                          // 1
    k_gemm_p<128><<<GEMM_GRID, 256, SM128>>>(xh, W0, isq, msg, NN);              // 2
    k_edgenode128<<<(NN * 32 + 255) / 256, 256>>>(rowptr, csr, isq, msg, b0, hbuf); // 3 <- profiled
    k_gemm_p<128><<<GEMM_GRID, 256, SM128>>>(hbuf, W1, isq, msg, NN);            // 4
    k_edgenode128<<<(NN * 32 + 255) / 256, 256>>>(rowptr, csr, isq, msg, b1, hbuf); // 5
    k_gemm_p<64><<<GEMM_GRID, 256, SM64>>>(hbuf, W2, isq, msg, NN);              // 6
    k_edgepool<<<(NN * 32 + 255) / 256, 256>>>(rowptr, csr, isq, msg, b2, batch, sums); // 7
    k_pool_fin<<<(NG * 64 + 255) / 256, 256>>>(sums, batch, (float*)d_out);      // 8
}

// round 17
// speedup vs baseline: 1.3876x; 1.0175x over previous
#include <cuda_runtime.h>
#include <cuda_fp16.h>
#include <cstdint>

#define NN 100000
#define NE 1600000
#define NG 256
#define SCAN_NB 98   // ceil(100000/1024)
#define NTILES 782   // ceil(100000/128)
#define GEMM_GRID 296

// ---------------- device scratch ----------------
__device__ __half g_xh[(size_t)NN * 128];    // x converted to fp16
__device__ __half g_msg[(size_t)NN * 128];   // xls = isq * (x@W), fp16
__device__ __half g_h[(size_t)NN * 128];     // h (fp16, GEMM input)
__device__ float  g_isq[NN];
__device__ int    g_cnti[NN];
__device__ int    g_fill[NN];
__device__ int    g_rowptr[NN + 1];
__device__ int    g_part[SCAN_NB + 2];
__device__ int    g_offs[SCAN_NB + 2];
__device__ int    g_csr[NE];                 // stores src<<5 (premultiplied row base)
__device__ float  g_sums[NG * 64];
__device__ int    g_sync[4];

// ---------------- helpers ----------------
__device__ __forceinline__ float tanh_hw(float x) {
    float y;
    asm("tanh.approx.f32 %0, %1;" : "=f"(y) : "f"(x));
    return y;
}
__device__ __forceinline__ float gelu_tanh(float x) {
    const float c = 0.7978845608028654f;
    float x3 = x * x * x;
    return 0.5f * x * (1.0f + tanh_hw(c * (x + 0.044715f * x3)));
}

__device__ __forceinline__ __half2 u2h(uint32_t v) { return *reinterpret_cast<__half2*>(&v); }

__device__ __forceinline__ void acc_h2x2(float4& acc, uint2 v) {
    float2 lo = __half22float2(u2h(v.x));
    float2 hi = __half22float2(u2h(v.y));
    acc.x += lo.x; acc.y += lo.y; acc.z += hi.x; acc.w += hi.y;
}

__device__ __forceinline__ void ldsm_x4(uint32_t* r, uint32_t addr) {
    asm volatile("ldmatrix.sync.aligned.m8n8.x4.shared.b16 {%0,%1,%2,%3}, [%4];"
                 : "=r"(r[0]), "=r"(r[1]), "=r"(r[2]), "=r"(r[3]) : "r"(addr));
}
__device__ __forceinline__ void ldsm_x4_t(uint32_t* r, uint32_t addr) {
    asm volatile("ldmatrix.sync.aligned.m8n8.x4.trans.shared.b16 {%0,%1,%2,%3}, [%4];"
                 : "=r"(r[0]), "=r"(r[1]), "=r"(r[2]), "=r"(r[3]) : "r"(addr));
}
__device__ __forceinline__ void mma_f16(float4& d, const uint32_t a[4], uint32_t b0, uint32_t b1) {
    asm volatile(
        "mma.sync.aligned.m16n8k16.row.col.f32.f16.f16.f32 "
        "{%0,%1,%2,%3},{%4,%5,%6,%7},{%8,%9},{%0,%1,%2,%3};"
        : "+f"(d.x), "+f"(d.y), "+f"(d.z), "+f"(d.w)
        : "r"(a[0]), "r"(a[1]), "r"(a[2]), "r"(a[3]), "r"(b0), "r"(b1));
}
__device__ __forceinline__ void cp_commit() { asm volatile("cp.async.commit_group;"); }
template <int N>
__device__ __forceinline__ void cp_wait() { asm volatile("cp.async.wait_group %0;" :: "n"(N)); }

// ---------------- fused x->fp16 convert + degree count ----------------
__global__ void k_prep(const float* __restrict__ x, __half* __restrict__ xh,
                       const int* __restrict__ dst, int* __restrict__ cnt) {
    int i = blockIdx.x * blockDim.x + threadIdx.x;
    if (i < NN * 32) {
        float4 v = __ldg(&((const float4*)x)[i]);
        __half2 h0 = __floats2half2_rn(v.x, v.y);
        __half2 h1 = __floats2half2_rn(v.z, v.w);
        uint2 o; o.x = *(uint32_t*)&h0; o.y = *(uint32_t*)&h1;
        ((uint2*)xh)[i] = o;
    }
    if (i < NE) atomicAdd(&cnt[dst[i]], 1);
}

// ---------------- single-pass scan (shfl) + isq + rowptr (98 co-resident blocks, runs ALONE) ----------------
__global__ __launch_bounds__(1024) void k_scan(
    const int* __restrict__ cnt, int* __restrict__ part, int* __restrict__ offs,
    float* __restrict__ isq, int* __restrict__ rowptr, int* __restrict__ sync) {
    __shared__ int wsum[32];
    __shared__ int is_last;
    int bid = blockIdx.x, t = threadIdx.x;
    int lane = t & 31, wid = t >> 5;
    int i = bid * 1024 + t;
    int v = (i < NN) ? cnt[i] : 0;
    if (i < NN) isq[i] = rsqrtf((float)v + 1.0f);

    int xscan = v;
    #pragma unroll
    for (int d = 1; d < 32; d <<= 1) {
        int y = __shfl_up_sync(0xffffffffu, xscan, d);
        if (lane >= d) xscan += y;
    }
    if (lane == 31) wsum[wid] = xscan;
    __syncthreads();
    if (wid == 0) {
        int y = wsum[lane];
        #pragma unroll
        for (int d = 1; d < 32; d <<= 1) {
            int z = __shfl_up_sync(0xffffffffu, y, d);
            if (lane >= d) y += z;
        }
        wsum[lane] = y;
    }
    __syncthreads();
    int incl = xscan + (wid > 0 ? wsum[wid - 1] : 0);
    if (t == 1023) part[bid] = incl;
    __syncthreads();

    if (t == 0) {
        __threadfence();
        int old = atomicAdd(&sync[0], 1);
        is_last = (old == SCAN_NB - 1) ? 1 : 0;
    }
    __syncthreads();
    if (is_last) {
        __shared__ int sp[128];
        if (t < 128) sp[t] = (t < SCAN_NB) ? part[t] : 0;
        __syncthreads();
        for (int off = 1; off < 128; off <<= 1) {
            int tv = (t >= off && t < 128) ? sp[t - off] : 0;
            __syncthreads();
            if (t < 128) sp[t] += tv;
            __syncthreads();
        }
        if (t < SCAN_NB) offs[t] = (t == 0) ? 0 : sp[t - 1];
        __threadfence();
        __syncthreads();
        if (t == 0) atomicExch(&sync[1], 1);
    }
    if (t == 0) {
        while (*(volatile int*)&sync[1] == 0) { }
    }
    __syncthreads();
    __threadfence();
    int myoff = offs[bid];
    if (i < NN) rowptr[i + 1] = incl + myoff;
    if (i == 0) rowptr[0] = 0;
}

// ---------------- CSR fill (no spins, co-schedulable) ----------------
__global__ void k_fill(const int* __restrict__ src, const int* __restrict__ dst,
                       const int* __restrict__ rowptr, int* __restrict__ fill,
                       int* __restrict__ csr) {
    int e = blockIdx.x * blockDim.x + threadIdx.x;
    if (e >= NE) return;
    int d = __ldg(&dst[e]);
    int pos = rowptr[d] + atomicAdd(&fill[d], 1);
    csr[pos] = __ldg(&src[e]) << 5;   // premultiplied row base
}

// ---------------- pipelined fp16 tensor-core GEMM ----------------
template <int COUT>
__global__ __launch_bounds__(256, 2) void k_gemm_p(
    const __half* __restrict__ X, const float* __restrict__ W,
    const float* __restrict__ s, __half* __restrict__ Y, int n) {
    constexpr int WS = COUT + 8;
    constexpr int NT = COUT / 8;
    constexpr int STAGE = 128 * 136;
    constexpr int CPR = COUT / 8;
    extern __shared__ __half smh[];
    __half* sW = smh;             // [128][WS]
    __half* sX0 = smh + 128 * WS; // 2 x [128][136]
    int tid = threadIdx.x, lane = tid & 31, warp = tid >> 5;

    uint32_t sx_base = (uint32_t)__cvta_generic_to_shared(sX0);
    uint32_t sw_base = (uint32_t)__cvta_generic_to_shared(sW);

    auto load_tile = [&](int tile, int stage) {
        int row0 = tile * 128;
        uint32_t sb = sx_base + (uint32_t)(stage * STAGE * 2);
        #pragma unroll
        for (int i = tid; i < 128 * 16; i += 256) {
            int r = i >> 4, c = i & 15;
            int gr = row0 + r;
            if (gr < n)
                asm volatile("cp.async.cg.shared.global [%0], [%1], 16;"
                             :: "r"(sb + (uint32_t)(r * 272 + c * 16)),
                                "l"(X + (size_t)gr * 128 + c * 8));
        }
        cp_commit();
    };

    const int G = gridDim.x;
    int t0 = blockIdx.x;
    if (t0 < NTILES) load_tile(t0, 0);

    for (int i = tid; i < 128 * (COUT / 4); i += 256) {
        int k = i / (COUT / 4), c4 = (i % (COUT / 4)) * 4;
        float4 wv = __ldg(&((const float4*)W)[i]);
        __half2 h0 = __floats2half2_rn(wv.x, wv.y);
        __half2 h1 = __floats2half2_rn(wv.z, wv.w);
        uint2 o; o.x = *(uint32_t*)&h0; o.y = *(uint32_t*)&h1;
        *(uint2*)&sW[k * WS + c4] = o;
    }

    int stage = 0;
    int lane15 = lane & 15, laneh = (lane >> 4) << 3;
    int rw = warp * 16;

    for (int t = t0; t < NTILES; t += G) {
        int tn = t + G;
        if (tn < NTILES) { load_tile(tn, stage ^ 1); cp_wait<1>(); }
        else             { cp_wait<0>(); }
        __syncthreads();

        float4 acc[NT];
        #pragma unroll
        for (int q = 0; q < NT; q++) acc[q] = make_float4(0.f, 0.f, 0.f, 0.f);

        uint32_t sxs = sx_base + (uint32_t)(stage * STAGE * 2);
        __half* sXp = sX0 + stage * STAGE;
        #pragma unroll
        for (int kt = 0; kt < 8; kt++) {
            uint32_t afr[4];
            ldsm_x4(afr, sxs + (uint32_t)(((rw + lane15) * 136 + kt * 16 + laneh) * 2));
            #pragma unroll
            for (int np = 0; np < NT / 2; np++) {
                uint32_t bfr[4];
                ldsm_x4_t(bfr, sw_base + (uint32_t)(((kt * 16 + lane15) * WS + np * 16 + laneh) * 2));
                mma_f16(acc[2 * np], afr, bfr[0], bfr[1]);
                mma_f16(acc[2 * np + 1], afr, bfr[2], bfr[3]);
            }
        }

        int qid = lane >> 2, tq = lane & 3;
        int row0 = t * 128;
        int r1 = row0 + rw + qid, r2 = r1 + 8;
        float s1v = (r1 < n) ? __ldg(&s[r1]) : 0.f;
        float s2v = (r2 < n) ? __ldg(&s[r2]) : 0.f;
        #pragma unroll
        for (int nt = 0; nt < NT; nt++) {
            int c = nt * 8 + 2 * tq;
            *(__half2*)&sXp[(rw + qid) * 136 + c]     = __floats2half2_rn(s1v * acc[nt].x, s1v * acc[nt].y);
            *(__half2*)&sXp[(rw + qid + 8) * 136 + c] = __floats2half2_rn(s2v * acc[nt].z, s2v * acc[nt].w);
        }
        __syncwarp();
        #pragma unroll
        for (int q = 0; q < 16 * CPR / 32; q++) {
            int idx = q * 32 + lane;
            int r = idx / CPR, c = idx % CPR;
            int gr = row0 + rw + r;
            if (gr < n)
                *(uint4*)&Y[(size_t)gr * COUT + c * 8] = *(uint4*)&sXp[(rw + r) * 136 + c * 8];
        }
        __syncthreads();
        stage ^= 1;
    }
}

// ---------------- fused edge gather + node epilogue (premultiplied csr, depth-2 tree) ----------------
__global__ __launch_bounds__(256) void k_edgenode128(
    const int* __restrict__ rp, const int* __restrict__ csr,
    const float* __restrict__ isq, const __half* __restrict__ msg,
    const float* __restrict__ b, __half* __restrict__ h) {
    int w = (blockIdx.x * blockDim.x + threadIdx.x) >> 5;
    int lane = threadIdx.x & 31;
    if (w >= NN) return;
    int e0 = __ldg(&rp[w]), e1 = __ldg(&rp[w + 1]);
    const uint2* M = (const uint2*)msg;
    float4 acc = make_float4(0.f, 0.f, 0.f, 0.f);
    acc_h2x2(acc, __ldg(&M[(unsigned)(w * 32 + lane)]));   // self

    for (int base = e0; base < e1; base += 32) {
        int n = e1 - base; if (n > 32) n = 32;
        int myidx = 0;
        if (lane < n) myidx = __ldg(&csr[base + lane]);   // premultiplied (src<<5)
        int j = 0;
        for (; j + 8 <= n; j += 8) {
            int ss[8]; uint2 vv[8];
            #pragma unroll
            for (int q = 0; q < 8; q++) ss[q] = __shfl_sync(0xffffffffu, myidx, j + q);
            #pragma unroll
            for (int q = 0; q < 8; q++) vv[q] = __ldg(&M[(unsigned)(ss[q] + lane)]);
            #pragma unroll
            for (int g = 0; g < 2; g++) {
                __half2 px = __hadd2(__hadd2(u2h(vv[4*g].x), u2h(vv[4*g+1].x)),
                                     __hadd2(u2h(vv[4*g+2].x), u2h(vv[4*g+3].x)));
                __half2 py = __hadd2(__hadd2(u2h(vv[4*g].y), u2h(vv[4*g+1].y)),
                                     __hadd2(u2h(vv[4*g+2].y), u2h(vv[4*g+3].y)));
                float2 fx = __half22float2(px);
                float2 fy = __half22float2(py);
                acc.x += fx.x; acc.y += fx.y; acc.z += fy.x; acc.w += fy.y;
            }
        }
        if (j + 4 <= n) {
            int ss[4]; uint2 vv[4];
            #pragma unroll
            for (int q = 0; q < 4; q++) ss[q] = __shfl_sync(0xffffffffu, myidx, j + q);
            #pragma unroll
            for (int q = 0; q < 4; q++) vv[q] = __ldg(&M[(unsigned)(ss[q] + lane)]);
            __half2 px = __hadd2(__hadd2(u2h(vv[0].x), u2h(vv[1].x)),
                                 __hadd2(u2h(vv[2].x), u2h(vv[3].x)));
            __half2 py = __hadd2(__hadd2(u2h(vv[0].y), u2h(vv[1].y)),
                                 __hadd2(u2h(vv[2].y), u2h(vv[3].y)));
            float2 fx = __half22float2(px);
            float2 fy = __half22float2(py);
            acc.x += fx.x; acc.y += fx.y; acc.z += fy.x; acc.w += fy.y;
            j += 4;
        }
        for (; j < n; j++) {
            int s0 = __shfl_sync(0xffffffffu, myidx, j);
            acc_h2x2(acc, __ldg(&M[(unsigned)(s0 + lane)]));
        }
    }
    float sc = __ldg(&isq[w]);
    float4 bb = __ldg(&((const float4*)b)[lane]);
    __half2 p0 = __floats2half2_rn(gelu_tanh(sc * acc.x + bb.x), gelu_tanh(sc * acc.y + bb.y));
    __half2 p1 = __floats2half2_rn(gelu_tanh(sc * acc.z + bb.z), gelu_tanh(sc * acc.w + bb.w));
    uint2 out; out.x = *(uint32_t*)&p0; out.y = *(uint32_t*)&p1;
    ((uint2*)h)[(size_t)w * 32 + lane] = out;
}

// final layer: gather (COUT=64) + gelu + fused mean-pool reduction into sums
__global__ __launch_bounds__(256) void k_edgepool(
    const int* __restrict__ rp, const int* __restrict__ csr,
    const float* __restrict__ isq, const __half* __restrict__ msg,
    const float* __restrict__ b, const int* __restrict__ batch,
    float* __restrict__ sums) {
    int w = (blockIdx.x * blockDim.x + threadIdx.x) >> 5;
    int lane = threadIdx.x & 31;
    if (w >= NN) return;
    int e0 = __ldg(&rp[w]), e1 = __ldg(&rp[w + 1]);
    const uint32_t* M = (const uint32_t*)msg;
    float2 acc = __half22float2(u2h(__ldg(&M[(unsigned)(w * 32 + lane)])));

    for (int base = e0; base < e1; base += 32) {
        int n = e1 - base; if (n > 32) n = 32;
        int myidx = 0;
        if (lane < n) myidx = __ldg(&csr[base + lane]);
        int j = 0;
        for (; j + 8 <= n; j += 8) {
            int ss[8]; uint32_t vv[8];
            #pragma unroll
            for (int q = 0; q < 8; q++) ss[q] = __shfl_sync(0xffffffffu, myidx, j + q);
            #pragma unroll
            for (int q = 0; q < 8; q++) vv[q] = __ldg(&M[(unsigned)(ss[q] + lane)]);
            #pragma unroll
            for (int g = 0; g < 2; g++) {
                __half2 p = __hadd2(__hadd2(u2h(vv[4*g]), u2h(vv[4*g+1])),
                                    __hadd2(u2h(vv[4*g+2]), u2h(vv[4*g+3])));
                float2 f = __half22float2(p);
                acc.x += f.x; acc.y += f.y;
            }
        }
        if (j + 4 <= n) {
            int ss[4]; uint32_t vv[4];
            #pragma unroll
            for (int q = 0; q < 4; q++) ss[q] = __shfl_sync(0xffffffffu, myidx, j + q);
            #pragma unroll
            for (int q = 0; q < 4; q++) vv[q] = __ldg(&M[(unsigned)(ss[q] + lane)]);
            __half2 p = __hadd2(__hadd2(u2h(vv[0]), u2h(vv[1])),
                                __hadd2(u2h(vv[2]), u2h(vv[3])));
            float2 f = __half22float2(p);
            acc.x += f.x; acc.y += f.y;
            j += 4;
        }
        for (; j < n; j++) {
            int s0 = __shfl_sync(0xffffffffu, myidx, j);
            float2 f = __half22float2(u2h(__ldg(&M[(unsigned)(s0 + lane)])));
            acc.x += f.x; acc.y += f.y;
        }
    }
    float sc = __ldg(&isq[w]);
    float2 bb = __ldg(&((const float2*)b)[lane]);
    float gx = gelu_tanh(sc * acc.x + bb.x);
    float gy = gelu_tanh(sc * acc.y + bb.y);
    int g = __ldg(&batch[w]);
    float* p = sums + (size_t)g * 64 + (size_t)lane * 2;
    asm volatile("red.global.add.v2.f32 [%0], {%1,%2};" :: "l"(p), "f"(gx), "f"(gy) : "memory");
}

// ---------------- pool finalize (counts via binary search, per-thread) ----------------
__global__ void k_pool_fin(const float* __restrict__ sums, const int* __restrict__ batch,
                           float* __restrict__ out) {
    int i = blockIdx.x * blockDim.x + threadIdx.x;
    if (i >= NG * 64) return;
    int g = i >> 6;
    int lo = 0, hi = NN;
    while (lo < hi) { int mid = (lo + hi) >> 1; if (__ldg(&batch[mid]) < g) lo = mid + 1; else hi = mid; }
    int a = lo;
    lo = 0; hi = NN;
    while (lo < hi) { int mid = (lo + hi) >> 1; if (__ldg(&batch[mid]) < g + 1) lo = mid + 1; else hi = mid; }
    float c = fmaxf((float)(lo - a), 1.0f);
    out[i] = sums[i] / c;
}

// ---------------- launch ----------------
extern "C" void kernel_launch(void* const* d_in, const int* in_sizes, int n_in,
                              void* d_out, int out_size) {
    const float* x = (const float*)d_in[0];
    const int* ei = (const int*)d_in[1];
    const int* batch = (const int*)d_in[2];
    const float* W0 = (const float*)d_in[3];
    const float* b0 = (const float*)d_in[4];
    const float* W1 = (const float*)d_in[5];
    const float* b1 = (const float*)d_in[6];
    const float* W2 = (const float*)d_in[7];
    const float* b2 = (const float*)d_in[8];
    const int* src = ei;
    const int* dst = ei + NE;

    __half *xh, *msg, *hbuf;
    float *isq, *sums;
    int *cnti, *fill, *rowptr, *part, *offs, *csr, *sync;
    cudaGetSymbolAddress((void**)&xh, g_xh);
    cudaGetSymbolAddress((void**)&msg, g_msg);
    cudaGetSymbolAddress((void**)&hbuf, g_h);
    cudaGetSymbolAddress((void**)&isq, g_isq);
    cudaGetSymbolAddress((void**)&cnti, g_cnti);
    cudaGetSymbolAddress((void**)&fill, g_fill);
    cudaGetSymbolAddress((void**)&rowptr, g_rowptr);
    cudaGetSymbolAddress((void**)&part, g_part);
    cudaGetSymbolAddress((void**)&offs, g_offs);
    cudaGetSymbolAddress((void**)&csr, g_csr);
    cudaGetSymbolAddress((void**)&sums, g_sums);
    cudaGetSymbolAddress((void**)&sync, g_sync);

    const int SM128 = (128 * 136 + 2 * 128 * 136) * 2;  // 104448
    const int SM64  = (128 * 72 + 2 * 128 * 136) * 2;   // 88064
    cudaFuncSetAttribute(k_gemm_p<128>, cudaFuncAttributeMaxDynamicSharedMemorySize, SM128);
    cudaFuncSetAttribute(k_gemm_p<64>, cudaFuncAttributeMaxDynamicSharedMemorySize, SM64);

    // lazily created side stream + events (first call is eager, before graph capture)
    static cudaStream_t s2 = nullptr;
    static cudaEvent_t evA = nullptr, evB = nullptr;
    if (s2 == nullptr) {
        cudaStreamCreateWithFlags(&s2, cudaStreamNonBlocking);
        cudaEventCreateWithFlags(&evA, cudaEventDisableTiming);
        cudaEventCreateWithFlags(&evB, cudaEventDisableTiming);
    }

    // memsets (not kernel launches)
    cudaMemsetAsync(cnti, 0, NN * sizeof(int));
    cudaMemsetAsync(fill, 0, NN * sizeof(int));
    cudaMemsetAsync(sums, 0, NG * 64 * sizeof(float));
    cudaMemsetAsync(sync, 0, 4 * sizeof(int));

    // kernel launches
    k_prep<<<(NN * 32 + 255) / 256, 256>>>(x, xh, dst, cnti);                    // 0
    k_scan<<<SCAN_NB, 1024>>>(cnti, part, offs, isq, rowptr, sync);              // 1 (runs alone)
    cudaEventRecord(evA, 0);
    cudaStreamWaitEvent(s2, evA, 0);
    k_fill<<<(NE + 255) / 256, 256, 0, s2>>>(src, dst, rowptr, fill, csr);       // 2 (s2, no spins)
    cudaEventRecord(evB, s2);
    k_gemm_p<128><<<GEMM_GRID, 256, SM128>>>(xh, W0, isq, msg, NN);              // 3 <- profiled (overlaps fill)
    cudaStreamWaitEvent(0, evB, 0);
    k_edgenode128<<<(NN * 32 + 255) / 256, 256>>>(rowptr, csr, isq, msg, b0, hbuf);
    k_gemm_p<128><<<GEMM_GRID, 256, SM128>>>(hbuf, W1, isq, msg, NN);
    k_edgenode128<<<(NN * 32 + 255) / 256, 256>>>(rowptr, csr, isq, msg, b1, hbuf);
    k_gemm_p<64><<<GEMM_GRID, 256, SM64>>>(hbuf, W2, isq, msg, NN);
    k_edgepool<<<(NN * 32 + 255) / 256, 256>>>(rowptr, csr, isq, msg, b2, batch, sums);
    k_pool_fin<<<(NG * 64 + 255) / 256, 256>>>(sums, batch, (float*)d_out);
}